// round 12
// baseline (speedup 1.0000x reference)
#include <cuda_runtime.h>
#include <math.h>

#define NSC   48
#define RMAX  11
#define NCTA  (3*NSC)
#define T     384

#define GW0_F4 4864        // 38 pairs * 512B
#define GW0_A  2560        // pairs 0..19
#define GW0_B  2304        // pairs 20..37
#define GW1_F4 8192        // 64 pairs * 512B = 128KB
#define PAN_F4 2560        // 40KB panel
#define DYN_SMEM ((GW1_F4 + PAN_F4) * 16)   // 172,032 bytes

typedef unsigned long long u64t;

__device__ float4 g_gw0p2[3*GW0_F4];
__device__ float4 g_gw1p2[3*GW1_F4];
__device__ __align__(16) float g_Wa_t[6*4096];
__device__ __align__(16) float g_w1_t[6*8192];
__device__ __align__(16) float g_w2_t[6*8192];
__device__ __align__(16) float g_rw1_t[3*4096];
__device__ float g_ba[6*64];
__device__ float g_outs[3ull*512*512*64];

__device__ __forceinline__ float sigmf(float v){
    return __fdividef(1.0f, 1.0f + __expf(-v));
}
__device__ __forceinline__ float tanhfast(float v){
    return 1.0f - __fdividef(2.0f, __expf(2.0f*v) + 1.0f);
}
__device__ __forceinline__ u64t fma2(u64t a, u64t b, u64t c){
    u64t d;
    asm("fma.rn.f32x2 %0, %1, %2, %3;" : "=l"(d) : "l"(a), "l"(b), "l"(c));
    return d;
}
__device__ __forceinline__ u64t pk2(float lo, float hi){
    u64t r; asm("mov.b64 %0, {%1, %2};" : "=l"(r) : "f"(lo), "f"(hi)); return r;
}
__device__ __forceinline__ float red2(u64t v){
    float lo, hi; asm("mov.b64 {%0, %1}, %2;" : "=f"(lo), "=f"(hi) : "l"(v)); return lo + hi;
}

template<int N>
__device__ __forceinline__ void cpyp(float4* d, const float4* __restrict__ s, int tid){
    #pragma unroll
    for (int i = 0; i < (N + T - 1)/T; i++){
        int j = tid + i*T;
        if (j < N) d[j] = s[j];
    }
}

// ---- pack gates: per k-pair block: FI plane [64 x 16B] then GO plane [64 x 16B] ----
__global__ void pack_gw_kernel(const float* __restrict__ gw0, const float* __restrict__ gw1){
    int i = blockIdx.x*blockDim.x + threadIdx.x;
    float* p0 = (float*)g_gw0p2;
    float* p1 = (float*)g_gw1p2;
    if (i < 3*76*256){
        int s = i/(76*256), rem = i%(76*256), k = rem/256, j = rem%256;
        int g = j>>6, m = j&63, p = k>>1, h = k&1;
        int plane = g>>1;
        p0[(s*38 + p)*512 + plane*256 + m*4 + ((g&1)<<1) + h] = gw0[i];
    }
    if (i < 3*128*256){
        int s = i/(128*256), rem = i%(128*256), k = rem/256, j = rem%256;
        int g = j>>6, m = j&63, p = k>>1, h = k&1;
        int plane = g>>1;
        p1[(s*64 + p)*512 + plane*256 + m*4 + ((g&1)<<1) + h] = gw1[i];
    }
}

// ---- pack stage weights into [p][colpair][wk0c0,wk1c0,wk0c1,wk1c1] ----
__global__ void pack_t_kernel(const float* __restrict__ w1, const float* __restrict__ w2,
                              const float* __restrict__ rw1){
    int i = blockIdx.x*blockDim.x + threadIdx.x;
    if (i < 6*64*128){
        int sl = i/(64*128), k = (i/128)%64, n = i%128;
        g_w1_t[((sl*32 + (k>>1))*64 + (n>>1))*4 + ((n&1)<<1) + (k&1)] = w1[i];
    }
    if (i < 6*128*64){
        int sl = i/(128*64), k = (i/64)%128, n = i%64;
        g_w2_t[((sl*64 + (k>>1))*32 + (n>>1))*4 + ((n&1)<<1) + (k&1)] = w2[i];
    }
    if (i < 3*64*64){
        int s = i/(64*64), k = (i/64)%64, n = i%64;
        g_rw1_t[((s*32 + (k>>1))*32 + (n>>1))*4 + ((n&1)<<1) + (k&1)] = rw1[i];
    }
}

__global__ void compute_wa_kernel(const float* __restrict__ mi_w, const float* __restrict__ mi_b,
                                  const float* __restrict__ mo_w, const float* __restrict__ mo_b){
    int sl = blockIdx.x;
    const float* miw = mi_w + (size_t)sl*64*192;
    const float* mow = mo_w + (size_t)sl*64*64;
    for (int idx = threadIdx.x; idx < 64*64; idx += blockDim.x){
        int k = idx>>6, n = idx&63;
        float acc = 0.f;
        #pragma unroll 8
        for (int j=0;j<64;j++) acc += miw[k*192 + 128 + j] * mow[j*64 + n];
        g_Wa_t[((sl*32 + (k>>1))*32 + (n>>1))*4 + ((n&1)<<1) + (k&1)] = acc;
    }
    if (threadIdx.x < 64){
        int n = threadIdx.x;
        float acc = mo_b[sl*64 + n];
        #pragma unroll 8
        for (int j=0;j<64;j++) acc += mi_b[sl*192 + 128 + j] * mow[j*64 + n];
        g_ba[sl*64 + n] = acc;
    }
}

__global__ void __launch_bounds__(T, 1) xlstm_kernel(
    const float* __restrict__ x,
    const float* __restrict__ gb0, const float* __restrict__ gb1,
    const float* __restrict__ b1,  const float* __restrict__ b2,
    const float* __restrict__ lag, const float* __restrict__ lab,
    const float* __restrict__ logw,const float* __restrict__ lob,
    const float* __restrict__ rw0, const float* __restrict__ rb0,
    const float* __restrict__ rb1)
{
    const int cta = blockIdx.x;
    const int s   = cta / NSC;
    const int ci  = cta % NSC;
    const int base  = (ci < 32) ? ci*11 : 352 + (ci-32)*10;
    const int nrows = (ci < 32) ? 11 : 10;
    const int tid  = threadIdx.x;
    const int m    = tid & 63;          // old mapping (LN chain, inp)
    const int rg   = tid >> 6;
    const int lane = tid & 31;
    const int wrp  = tid >> 5;

    // ---- lane-row split mappings ----
    const int rsub = lane >> 4;         // 0..1 (upper lanes duplicate weight addrs)
    const int cl   = lane & 15;         // col-lane
    // gates/ff1: 4 col-quarters x 3 row groups
    const int cq   = wrp & 3;           // 0..3
    const int rowg = wrp >> 2;          // 0..2
    const int gm   = cq*16 + cl;        // gate col 0..63
    const int fcp  = cq*16 + cl;        // ff1 colpair 0..63
    const int fn2  = fcp*2;
    const int gr0  = rowg + 3*rsub;     // 0..5 (always valid)
    const int gr1  = gr0 + 6;           // 6..11
    const bool gv1 = (gr1 < nrows);
    const int cgr1 = gv1 ? gr1 : 0;
    // attn/ff2/out: 2 col-halves x 6 row groups
    const int ch   = wrp & 1;
    const int rgrp = wrp >> 1;          // 0..5
    const int scp  = ch*16 + cl;        // colpair 0..31
    const int sm2  = scp*2;
    const int srow = rgrp + 6*rsub;     // 0..11
    const bool sv  = (srow < nrows);
    const int csrow= sv ? srow : 0;

    extern __shared__ float4 dynsm[];
    float4* s_gw1 = dynsm;               // resident 128KB (plane-split pairs)
    float4* pan4  = dynsm + GW1_F4;      // 40KB panel
    const ulonglong2* gw1u = (const ulonglong2*)s_gw1;
    const ulonglong2* panu = (const ulonglong2*)pan4;

    __shared__ __align__(16) float sh_h0[RMAX][64], sh_h1[RMAX][64];
    __shared__ __align__(16) float sh_x[RMAX][12];
    __shared__ __align__(16) float sh_hy[RMAX][64];
    __shared__ __align__(16) float sh_a[RMAX][64];
    __shared__ __align__(16) float sh_t1[RMAX][128];
    __shared__ __align__(16) float sh_inp[RMAX][64];
    __shared__ float sh_stat[RMAX][2];
    __shared__ __align__(16) float sb_ba[2][64];
    __shared__ __align__(16) float sb_b1[2][128];
    __shared__ __align__(16) float sb_b2[2][64];
    __shared__ __align__(16) float sb_rb1[64];
    __shared__ __align__(16) float s_rw0[12*64];
    __shared__ __align__(16) float s_rw1[64*64];   // k-pair transposed

    {
        const float4* g1 = g_gw1p2 + (size_t)s*GW1_F4;
        for (int i=tid;i<GW1_F4;i+=T) s_gw1[i] = g1[i];
        const float* rw1s = g_rw1_t + (size_t)s*4096;
        for (int i=tid;i<4096;i+=T) s_rw1[i] = rw1s[i];
        const float* rw0s = rw0 + (size_t)s*768;
        for (int i=tid;i<768;i+=T) s_rw0[i] = rw0s[i];
        for (int i = tid; i < RMAX*64; i += T){ ((float*)sh_h0)[i] = 0.f; ((float*)sh_h1)[i] = 0.f; }
        if (tid < 128){
            sb_b1[0][tid] = b1[(s*2+0)*128 + tid];
            sb_b1[1][tid] = b1[(s*2+1)*128 + tid];
        }
        if (tid < 64){
            sb_ba[0][tid] = g_ba[(s*2+0)*64 + tid];
            sb_ba[1][tid] = g_ba[(s*2+1)*64 + tid];
            sb_b2[0][tid] = b2[(s*2+0)*64 + tid];
            sb_b2[1][tid] = b2[(s*2+1)*64 + tid];
            sb_rb1[tid]   = rb1[s*64 + tid];
        }
    }
    // gate biases (col = gm)
    const float r_gb0f = gb0[s*256 + gm],     r_gb0i = gb0[s*256 + 64 + gm];
    const float r_gb0g = gb0[s*256 + 128+gm], r_gb0o = gb0[s*256 + 192 + gm];
    const float r_gb1f = gb1[s*256 + gm],     r_gb1i = gb1[s*256 + 64 + gm];
    const float r_gb1g = gb1[s*256 + 128+gm], r_gb1o = gb1[s*256 + 192 + gm];
    // LN params (old mapping, col=m)
    const float r_lag0 = lag[(s*2+0)*64+m],  r_lag1 = lag[(s*2+1)*64+m];
    const float r_lab0 = lab[(s*2+0)*64+m],  r_lab1 = lab[(s*2+1)*64+m];
    const float r_log0 = logw[(s*2+0)*64+m], r_log1 = logw[(s*2+1)*64+m];
    const float r_lob0 = lob[(s*2+0)*64+m],  r_lob1 = lob[(s*2+1)*64+m];
    const float r_rb0  = rb0[s*64+m];
    __syncthreads();

    // old-mapping rows (LN chain + inp)
    int myr[2]; int nmy = 0;
    #pragma unroll
    for (int q=0;q<2;q++){ int r = rg + 6*q; myr[q] = (r < nrows) ? r : (nrows-1); if (r < nrows) nmy = q+1; }

    // cell states for gate rows (gr0 always valid; gr1 clamped)
    float c0A = 0.f, c0B = 0.f, c1A = 0.f, c1B = 0.f;

    const float4* gw0g  = g_gw0p2 + (size_t)s*GW0_F4;
    const float4* Wa0_4 = (const float4*)g_Wa_t + (size_t)(s*2+0)*1024;
    const float4* Wa1_4 = (const float4*)g_Wa_t + (size_t)(s*2+1)*1024;
    const float4* w10_4 = (const float4*)g_w1_t + (size_t)(s*2+0)*2048;
    const float4* w11_4 = (const float4*)g_w1_t + (size_t)(s*2+1)*2048;
    const float4* w20_4 = (const float4*)g_w2_t + (size_t)(s*2+0)*2048;
    const float4* w21_4 = (const float4*)g_w2_t + (size_t)(s*2+1)*2048;

    const int Li  = (s==0) ? 170 : (s==1 ? 512 : 256);
    const int st0 = (s==0) ? 342 : (s==1 ? 0   : 256);
    const float scf = (float)Li / 512.0f;

    float* outbase = g_outs + ((size_t)s*512 + base)*512*64;

    auto ln_pass = [&](){
        if (wrp < nrows){
            int r = wrp;
            float va = sh_hy[r][lane], vb = sh_hy[r][lane+32];
            float sm = va + vb, sq = va*va + vb*vb;
            #pragma unroll
            for (int o=16;o;o>>=1){
                sm += __shfl_xor_sync(0xffffffffu, sm, o);
                sq += __shfl_xor_sync(0xffffffffu, sq, o);
            }
            if (lane == 0){
                float mean = sm * 0.015625f;
                float var  = sq * 0.015625f - mean*mean;
                sh_stat[r][0] = mean;
                sh_stat[r][1] = rsqrtf(var + 1e-5f);
            }
        }
    };
    auto ln_chain = [&](float (*hstate)[64], float* hn_out,
                        float lag_r, float lab_r, float log_r, float lob_r){
        ln_pass();
        __syncthreads();
        #pragma unroll
        for (int q=0;q<2;q++){
            int r = myr[q];
            float v  = sh_hy[r][m];
            float ln = (v - sh_stat[r][0]) * sh_stat[r][1] * lag_r + lab_r;
            float yv = ln + hstate[r][m];
            if (q < nmy) sh_hy[r][m] = yv;
        }
        __syncthreads();
        ln_pass();
        __syncthreads();
        #pragma unroll
        for (int q=0;q<2;q++){
            int r = myr[q];
            float yv = sh_hy[r][m];
            float hn = (yv - sh_stat[r][0]) * sh_stat[r][1] * log_r + lob_r;
            hn_out[q] = hn;
            if (q < nmy) hstate[r][m] = hn;
        }
    };

    // attn: a[srow][sm2..+1] = ba + hy[srow]@Wa  (lane-row split, redundancy 6)
    auto attn_stage = [&](int l){
        u64t a0 = pk2(sb_ba[l][sm2], 0.f), a1 = pk2(sb_ba[l][sm2+1], 0.f);
        #pragma unroll 8
        for (int p=0;p<32;p++){
            ulonglong2 w = panu[p*32 + scp];
            u64t z = *(const u64t*)&sh_hy[csrow][2*p];
            a0 = fma2(z, w.x, a0);
            a1 = fma2(z, w.y, a1);
        }
        if (sv) *(float2*)&sh_a[srow][sm2] = make_float2(red2(a0), red2(a1));
    };
    // ff1: rows gr0/gr1, colpair fcp (redundancy 3)
    auto ff1_stage = [&](int l){
        u64t t00 = pk2(sb_b1[l][fn2], 0.f), t01 = pk2(sb_b1[l][fn2+1], 0.f);
        u64t t10 = t00, t11 = t01;
        #pragma unroll 8
        for (int p=0;p<32;p++){
            ulonglong2 w = panu[p*64 + fcp];
            u64t zA = *(const u64t*)&sh_a[gr0][2*p];
            u64t zB = *(const u64t*)&sh_a[cgr1][2*p];
            t00 = fma2(zA, w.x, t00); t01 = fma2(zA, w.y, t01);
            t10 = fma2(zB, w.x, t10); t11 = fma2(zB, w.y, t11);
        }
        const float c = 0.7071067811865475f;
        float v00 = red2(t00), v01 = red2(t01), v10 = red2(t10), v11 = red2(t11);
        float g00 = 0.5f*v00*(1.0f + erff(v00*c));
        float g01 = 0.5f*v01*(1.0f + erff(v01*c));
        *(float2*)&sh_t1[gr0][fn2] = make_float2(g00, g01);
        if (gv1){
            float g10 = 0.5f*v10*(1.0f + erff(v10*c));
            float g11 = 0.5f*v11*(1.0f + erff(v11*c));
            *(float2*)&sh_t1[gr1][fn2] = make_float2(g10, g11);
        }
    };
    // ff2: like attn, 64 k-pairs from sh_t1
    auto ff2_stage = [&](int l){
        u64t a0 = pk2(sb_b2[l][sm2], 0.f), a1 = pk2(sb_b2[l][sm2+1], 0.f);
        #pragma unroll 8
        for (int p=0;p<64;p++){
            ulonglong2 w = panu[p*32 + scp];
            u64t z = *(const u64t*)&sh_t1[csrow][2*p];
            a0 = fma2(z, w.x, a0);
            a1 = fma2(z, w.y, a1);
        }
        if (sv) *(float2*)&sh_hy[srow][sm2] = make_float2(red2(a0), red2(a1));
    };

    for (int t=0; t<512; t++){
        cpyp<GW0_A>(pan4, gw0g, tid);
        {
            float srcf = fmaxf((t + 0.5f) * scf - 0.5f, 0.0f);
            int i0 = (int)srcf;
            if (i0 > Li-1) i0 = Li-1;
            int i1 = min(i0+1, Li-1);
            float wu = srcf - (float)i0;
            if (tid < nrows*12){
                int r = tid/12, k = tid%12;
                const float* xb = x + ((size_t)(base+r)*512 + st0)*12;
                float va = xb[i0*12 + k], vb = xb[i1*12 + k];
                sh_x[r][k] = va*(1.0f - wu) + vb*wu;
            }
        }
        __syncthreads();                              // S1: gw0A + sh_x ready

        // ---- gates layer 0 (f32x2, lane-row split, redundancy 3) ----
        u64t aF0 = pk2(r_gb0f,0.f), aI0 = pk2(r_gb0i,0.f), aG0 = pk2(r_gb0g,0.f), aO0 = pk2(r_gb0o,0.f);
        u64t aF1 = aF0, aI1 = aI0, aG1 = aG0, aO1 = aO0;
        #pragma unroll
        for (int p=0;p<6;p++){                        // k 0..11 from sh_x
            ulonglong2 wfi = panu[p*128 + gm], wgo = panu[p*128 + 64 + gm];
            u64t z0 = *(const u64t*)&sh_x[gr0][2*p];
            u64t z1 = *(const u64t*)&sh_x[cgr1][2*p];
            aF0 = fma2(z0, wfi.x, aF0); aI0 = fma2(z0, wfi.y, aI0);
            aG0 = fma2(z0, wgo.x, aG0); aO0 = fma2(z0, wgo.y, aO0);
            aF1 = fma2(z1, wfi.x, aF1); aI1 = fma2(z1, wfi.y, aI1);
            aG1 = fma2(z1, wgo.x, aG1); aO1 = fma2(z1, wgo.y, aO1);
        }
        #pragma unroll 7
        for (int p=6;p<20;p++){                       // k 12..39 from sh_h0
            ulonglong2 wfi = panu[p*128 + gm], wgo = panu[p*128 + 64 + gm];
            u64t z0 = *(const u64t*)&sh_h0[gr0][2*p-12];
            u64t z1 = *(const u64t*)&sh_h0[cgr1][2*p-12];
            aF0 = fma2(z0, wfi.x, aF0); aI0 = fma2(z0, wfi.y, aI0);
            aG0 = fma2(z0, wgo.x, aG0); aO0 = fma2(z0, wgo.y, aO0);
            aF1 = fma2(z1, wfi.x, aF1); aI1 = fma2(z1, wfi.y, aI1);
            aG1 = fma2(z1, wgo.x, aG1); aO1 = fma2(z1, wgo.y, aO1);
        }
        __syncthreads();                              // S2: panel free
        cpyp<GW0_B>(pan4, gw0g + GW0_A, tid);
        __syncthreads();                              // S3: gw0B ready
        #pragma unroll 6
        for (int p=20;p<38;p++){                      // k 40..75 from sh_h0
            ulonglong2 wfi = panu[(p-20)*128 + gm], wgo = panu[(p-20)*128 + 64 + gm];
            u64t z0 = *(const u64t*)&sh_h0[gr0][2*p-12];
            u64t z1 = *(const u64t*)&sh_h0[cgr1][2*p-12];
            aF0 = fma2(z0, wfi.x, aF0); aI0 = fma2(z0, wfi.y, aI0);
            aG0 = fma2(z0, wgo.x, aG0); aO0 = fma2(z0, wgo.y, aO0);
            aF1 = fma2(z1, wfi.x, aF1); aI1 = fma2(z1, wfi.y, aI1);
            aG1 = fma2(z1, wgo.x, aG1); aO1 = fma2(z1, wgo.y, aO1);
        }
        {
            float cn0 = sigmf(red2(aF0))*c0A + sigmf(red2(aI0))*tanhfast(red2(aG0));
            float ht0 = sigmf(red2(aO0))*tanhfast(cn0);
            float cn1 = sigmf(red2(aF1))*c0B + sigmf(red2(aI1))*tanhfast(red2(aG1));
            float ht1 = sigmf(red2(aO1))*tanhfast(cn1);
            c0A = cn0; sh_hy[gr0][gm] = ht0;
            if (gv1){ c0B = cn1; sh_hy[gr1][gm] = ht1; }
        }
        __syncthreads();                              // S4
        cpyp<1024>(pan4, Wa0_4, tid);
        __syncthreads();                              // S5
        attn_stage(0);
        __syncthreads();                              // S6
        cpyp<2048>(pan4, w10_4, tid);
        __syncthreads();                              // S7
        ff1_stage(0);
        __syncthreads();                              // S8
        cpyp<2048>(pan4, w20_4, tid);
        __syncthreads();                              // S9
        ff2_stage(0);
        __syncthreads();                              // S10
        float h0n[2];
        ln_chain(sh_h0, h0n, r_lag0, r_lab0, r_log0, r_lob0);
        #pragma unroll
        for (int q=0;q<2;q++){
            int r = myr[q];
            float acc = h0n[q] + r_rb0;
            #pragma unroll
            for (int k=0;k<12;k++) acc += sh_x[r][k] * s_rw0[k*64 + m];
            if (q < nmy) sh_inp[r][m] = acc;
        }
        __syncthreads();                              // S14
        cpyp<1024>(pan4, Wa1_4, tid);

        // ---- gates layer 1 (resident, f32x2, lane-row split) ----
        u64t bF0 = pk2(r_gb1f,0.f), bI0 = pk2(r_gb1i,0.f), bG0 = pk2(r_gb1g,0.f), bO0 = pk2(r_gb1o,0.f);
        u64t bF1 = bF0, bI1 = bI0, bG1 = bG0, bO1 = bO0;
        #pragma unroll 8
        for (int p=0;p<32;p++){                       // k 0..63 from sh_inp
            ulonglong2 wfi = gw1u[p*128 + gm], wgo = gw1u[p*128 + 64 + gm];
            u64t z0 = *(const u64t*)&sh_inp[gr0][2*p];
            u64t z1 = *(const u64t*)&sh_inp[cgr1][2*p];
            bF0 = fma2(z0, wfi.x, bF0); bI0 = fma2(z0, wfi.y, bI0);
            bG0 = fma2(z0, wgo.x, bG0); bO0 = fma2(z0, wgo.y, bO0);
            bF1 = fma2(z1, wfi.x, bF1); bI1 = fma2(z1, wfi.y, bI1);
            bG1 = fma2(z1, wgo.x, bG1); bO1 = fma2(z1, wgo.y, bO1);
        }
        #pragma unroll 8
        for (int p=32;p<64;p++){                      // k 64..127 from sh_h1
            ulonglong2 wfi = gw1u[p*128 + gm], wgo = gw1u[p*128 + 64 + gm];
            u64t z0 = *(const u64t*)&sh_h1[gr0][2*p-64];
            u64t z1 = *(const u64t*)&sh_h1[cgr1][2*p-64];
            bF0 = fma2(z0, wfi.x, bF0); bI0 = fma2(z0, wfi.y, bI0);
            bG0 = fma2(z0, wgo.x, bG0); bO0 = fma2(z0, wgo.y, bO0);
            bF1 = fma2(z1, wfi.x, bF1); bI1 = fma2(z1, wfi.y, bI1);
            bG1 = fma2(z1, wgo.x, bG1); bO1 = fma2(z1, wgo.y, bO1);
        }
        {
            float cn0 = sigmf(red2(bF0))*c1A + sigmf(red2(bI0))*tanhfast(red2(bG0));
            float ht0 = sigmf(red2(bO0))*tanhfast(cn0);
            float cn1 = sigmf(red2(bF1))*c1B + sigmf(red2(bI1))*tanhfast(red2(bG1));
            float ht1 = sigmf(red2(bO1))*tanhfast(cn1);
            c1A = cn0; sh_hy[gr0][gm] = ht0;
            if (gv1){ c1B = cn1; sh_hy[gr1][gm] = ht1; }
        }
        __syncthreads();                              // S15: Wa1 + hy ready
        attn_stage(1);
        __syncthreads();                              // S16
        cpyp<2048>(pan4, w11_4, tid);
        __syncthreads();                              // S17
        ff1_stage(1);
        __syncthreads();                              // S18
        cpyp<2048>(pan4, w21_4, tid);
        __syncthreads();                              // S19
        ff2_stage(1);
        __syncthreads();                              // S20
        float h1n[2];
        ln_chain(sh_h1, h1n, r_lag1, r_lab1, r_log1, r_lob1);
        __syncthreads();                              // S24

        // ---- out = h1 + inp@rw1 + rb1 (lane-row split) ----
        {
            u64t a0 = pk2(sb_rb1[sm2]   + sh_h1[csrow][sm2],   0.f);
            u64t a1 = pk2(sb_rb1[sm2+1] + sh_h1[csrow][sm2+1], 0.f);
            const ulonglong2* rwu = (const ulonglong2*)s_rw1;
            #pragma unroll 8
            for (int p=0;p<32;p++){
                ulonglong2 w = rwu[p*32 + scp];
                u64t z = *(const u64t*)&sh_inp[csrow][2*p];
                a0 = fma2(z, w.x, a0);
                a1 = fma2(z, w.y, a1);
            }
            if (sv) ((float2*)(outbase + ((size_t)srow*512 + t)*64))[scp] = make_float2(red2(a0), red2(a1));
        }
        __syncthreads();                              // S25
    }
}

__global__ void merge_kernel(const float* __restrict__ attn_w, float* __restrict__ out){
    int warp = (blockIdx.x*blockDim.x + threadIdx.x) >> 5;
    int lane = threadIdx.x & 31;
    if (warp >= 512*512) return;
    const size_t SS = 512ull*512*64;
    const float* p = g_outs + (size_t)warp*64;
    float aw0 = attn_w[lane], aw1 = attn_w[lane+32];
    float v0[3], v1[3], sc[3];
    #pragma unroll
    for (int si=0; si<3; si++){
        v0[si] = p[si*SS + lane];
        v1[si] = p[si*SS + lane + 32];
        float d = v0[si]*aw0 + v1[si]*aw1;
        #pragma unroll
        for (int o=16;o;o>>=1) d += __shfl_xor_sync(0xffffffffu, d, o);
        sc[si] = d;
    }
    float mx = fmaxf(sc[0], fmaxf(sc[1], sc[2]));
    float e0 = __expf(sc[0]-mx), e1 = __expf(sc[1]-mx), e2 = __expf(sc[2]-mx);
    float inv = __fdividef(1.0f, e0+e1+e2);
    float wt0 = e0*inv, wt1 = e1*inv, wt2 = e2*inv;
    out[(size_t)warp*64 + lane]      = v0[0]*wt0 + v0[1]*wt1 + v0[2]*wt2;
    out[(size_t)warp*64 + lane + 32] = v1[0]*wt0 + v1[1]*wt1 + v1[2]*wt2;
}

extern "C" void kernel_launch(void* const* d_in, const int* in_sizes, int n_in,
                              void* d_out, int out_size){
    const float* x     = (const float*)d_in[0];
    const float* gw0   = (const float*)d_in[1];
    const float* gb0   = (const float*)d_in[2];
    const float* gw1   = (const float*)d_in[3];
    const float* gb1   = (const float*)d_in[4];
    const float* mi_w  = (const float*)d_in[5];
    const float* mi_b  = (const float*)d_in[6];
    const float* mo_w  = (const float*)d_in[7];
    const float* mo_b  = (const float*)d_in[8];
    const float* w1    = (const float*)d_in[9];
    const float* b1    = (const float*)d_in[10];
    const float* w2    = (const float*)d_in[11];
    const float* b2    = (const float*)d_in[12];
    const float* lag   = (const float*)d_in[13];
    const float* lab   = (const float*)d_in[14];
    const float* logw  = (const float*)d_in[15];
    const float* lob   = (const float*)d_in[16];
    const float* rw0   = (const float*)d_in[17];
    const float* rb0   = (const float*)d_in[18];
    const float* rw1   = (const float*)d_in[19];
    const float* rb1   = (const float*)d_in[20];
    const float* attnw = (const float*)d_in[21];
    float* out = (float*)d_out;

    static int smem_set = 0;
    if (!smem_set){
        cudaFuncSetAttribute(xlstm_kernel, cudaFuncAttributeMaxDynamicSharedMemorySize, DYN_SMEM);
        smem_set = 1;
    }

    pack_gw_kernel<<<(3*128*256 + 255)/256, 256>>>(gw0, gw1);
    pack_t_kernel<<<(6*64*128 + 255)/256, 256>>>(w1, w2, rw1);
    compute_wa_kernel<<<6, 256>>>(mi_w, mi_b, mo_w, mo_b);
    xlstm_kernel<<<NCTA, T, DYN_SMEM>>>(x, gb0, gb1, b1, b2,
                                        lag, lab, logw, lob, rw0, rb0, rb1);
    merge_kernel<<<(512*512*32 + 255)/256, 256>>>(attnw, out);
}

// round 13
// speedup vs baseline: 1.2840x; 1.2840x over previous
#include <cuda_runtime.h>
#include <math.h>

#define NSC   48
#define RMAX  11
#define NCTA  (3*NSC)
#define T     256

#define GW0_F4 4864        // 38 pairs * 512B
#define GW0_A  2560        // pairs 0..19
#define GW0_B  2304        // pairs 20..37
#define GW1_F4 8192        // 64 pairs * 512B = 128KB
#define PAN_F4 2560        // 40KB panel
#define DYN_SMEM ((GW1_F4 + PAN_F4) * 16)   // 172,032 bytes

typedef unsigned long long u64t;

__device__ float4 g_gw0p2[3*GW0_F4];
__device__ float4 g_gw1p2[3*GW1_F4];
__device__ __align__(16) float g_Wa_t[6*4096];
__device__ __align__(16) float g_w1_t[6*8192];
__device__ __align__(16) float g_w2_t[6*8192];
__device__ __align__(16) float g_rw1_t[3*4096];
__device__ float g_ba[6*64];
__device__ float g_outs[3ull*512*512*64];

__device__ __forceinline__ float sigmf(float v){
    return __fdividef(1.0f, 1.0f + __expf(-v));
}
__device__ __forceinline__ float tanhfast(float v){
    return 1.0f - __fdividef(2.0f, __expf(2.0f*v) + 1.0f);
}
__device__ __forceinline__ u64t fma2(u64t a, u64t b, u64t c){
    u64t d;
    asm("fma.rn.f32x2 %0, %1, %2, %3;" : "=l"(d) : "l"(a), "l"(b), "l"(c));
    return d;
}
__device__ __forceinline__ u64t pk2(float lo, float hi){
    u64t r; asm("mov.b64 %0, {%1, %2};" : "=l"(r) : "f"(lo), "f"(hi)); return r;
}
__device__ __forceinline__ float red2(u64t v){
    float lo, hi; asm("mov.b64 {%0, %1}, %2;" : "=f"(lo), "=f"(hi) : "l"(v)); return lo + hi;
}

template<int N>
__device__ __forceinline__ void cpyp(float4* d, const float4* __restrict__ s, int tid){
    #pragma unroll
    for (int i = 0; i < (N + T - 1)/T; i++){
        int j = tid + i*T;
        if (j < N) d[j] = s[j];
    }
}

// ---- pack gates: per k-pair block: FI plane [64 x 16B] then GO plane [64 x 16B] ----
__global__ void pack_gw_kernel(const float* __restrict__ gw0, const float* __restrict__ gw1){
    int i = blockIdx.x*blockDim.x + threadIdx.x;
    float* p0 = (float*)g_gw0p2;
    float* p1 = (float*)g_gw1p2;
    if (i < 3*76*256){
        int s = i/(76*256), rem = i%(76*256), k = rem/256, j = rem%256;
        int g = j>>6, m = j&63, p = k>>1, h = k&1;
        int plane = g>>1;
        p0[(s*38 + p)*512 + plane*256 + m*4 + ((g&1)<<1) + h] = gw0[i];
    }
    if (i < 3*128*256){
        int s = i/(128*256), rem = i%(128*256), k = rem/256, j = rem%256;
        int g = j>>6, m = j&63, p = k>>1, h = k&1;
        int plane = g>>1;
        p1[(s*64 + p)*512 + plane*256 + m*4 + ((g&1)<<1) + h] = gw1[i];
    }
}

// ---- pack stage weights into [p][colpair][wk0c0,wk1c0,wk0c1,wk1c1] ----
__global__ void pack_t_kernel(const float* __restrict__ w1, const float* __restrict__ w2,
                              const float* __restrict__ rw1){
    int i = blockIdx.x*blockDim.x + threadIdx.x;
    if (i < 6*64*128){
        int sl = i/(64*128), k = (i/128)%64, n = i%128;
        g_w1_t[((sl*32 + (k>>1))*64 + (n>>1))*4 + ((n&1)<<1) + (k&1)] = w1[i];
    }
    if (i < 6*128*64){
        int sl = i/(128*64), k = (i/64)%128, n = i%64;
        g_w2_t[((sl*64 + (k>>1))*32 + (n>>1))*4 + ((n&1)<<1) + (k&1)] = w2[i];
    }
    if (i < 3*64*64){
        int s = i/(64*64), k = (i/64)%64, n = i%64;
        g_rw1_t[((s*32 + (k>>1))*32 + (n>>1))*4 + ((n&1)<<1) + (k&1)] = rw1[i];
    }
}

__global__ void compute_wa_kernel(const float* __restrict__ mi_w, const float* __restrict__ mi_b,
                                  const float* __restrict__ mo_w, const float* __restrict__ mo_b){
    int sl = blockIdx.x;
    const float* miw = mi_w + (size_t)sl*64*192;
    const float* mow = mo_w + (size_t)sl*64*64;
    for (int idx = threadIdx.x; idx < 64*64; idx += blockDim.x){
        int k = idx>>6, n = idx&63;
        float acc = 0.f;
        #pragma unroll 8
        for (int j=0;j<64;j++) acc += miw[k*192 + 128 + j] * mow[j*64 + n];
        g_Wa_t[((sl*32 + (k>>1))*32 + (n>>1))*4 + ((n&1)<<1) + (k&1)] = acc;
    }
    if (threadIdx.x < 64){
        int n = threadIdx.x;
        float acc = mo_b[sl*64 + n];
        #pragma unroll 8
        for (int j=0;j<64;j++) acc += mi_b[sl*192 + 128 + j] * mow[j*64 + n];
        g_ba[sl*64 + n] = acc;
    }
}

__global__ void __launch_bounds__(T, 1) xlstm_kernel(
    const float* __restrict__ x,
    const float* __restrict__ gb0, const float* __restrict__ gb1,
    const float* __restrict__ b1,  const float* __restrict__ b2,
    const float* __restrict__ lag, const float* __restrict__ lab,
    const float* __restrict__ logw,const float* __restrict__ lob,
    const float* __restrict__ rw0, const float* __restrict__ rb0,
    const float* __restrict__ rb1)
{
    const int cta = blockIdx.x;
    const int s   = cta / NSC;
    const int ci  = cta % NSC;
    const int base  = (ci < 32) ? ci*11 : 352 + (ci-32)*10;
    const int nrows = (ci < 32) ? 11 : 10;
    const int tid  = threadIdx.x;
    const int m    = tid & 63;          // old mapping (LN chain, inp)
    const int rg   = tid >> 6;          // 0..3
    const int lane = tid & 31;
    const int wrp  = tid >> 5;          // 0..7

    // gates / ff1: 2 col-halves x 4 row-groups, 3 rows/thread
    const int colh = wrp & 1;
    const int rowg = wrp >> 1;          // 0..3
    const int gm   = colh*32 + lane;    // gate col / ff1 colpair
    const int fn2  = gm*2;
    int grow[3]; bool gvr[3];
    #pragma unroll
    for (int j=0;j<3;j++){ int r = rowg + 4*j; gvr[j] = (r < nrows); grow[j] = gvr[j] ? r : 0; }

    // attn / ff2 / out: 4 warps x 3 rows, lane = colpair
    const bool sact = (wrp < 4);
    const int scp   = lane;
    const int sm2   = lane*2;
    int srw[3]; bool svr[3];
    #pragma unroll
    for (int j=0;j<3;j++){ int r = wrp + 4*j; svr[j] = sact && (r < nrows); srw[j] = (r < nrows) ? r : 0; }

    extern __shared__ float4 dynsm[];
    float4* s_gw1 = dynsm;               // resident 128KB (plane-split pairs)
    float4* pan4  = dynsm + GW1_F4;      // 40KB panel
    const ulonglong2* gw1u = (const ulonglong2*)s_gw1;
    const ulonglong2* panu = (const ulonglong2*)pan4;

    __shared__ __align__(16) float sh_h0[RMAX][64], sh_h1[RMAX][64];
    __shared__ __align__(16) float sh_x[RMAX][12];
    __shared__ __align__(16) float sh_hy[RMAX][64];
    __shared__ __align__(16) float sh_a[RMAX][64];
    __shared__ __align__(16) float sh_t1[RMAX][128];
    __shared__ __align__(16) float sh_inp[RMAX][64];
    __shared__ float sh_stat[RMAX][2];
    __shared__ __align__(16) float sb_ba[2][64];
    __shared__ __align__(16) float sb_b1[2][128];
    __shared__ __align__(16) float sb_b2[2][64];
    __shared__ __align__(16) float sb_rb1[64];
    __shared__ __align__(16) float s_rw0[12*64];
    __shared__ __align__(16) float s_rw1[64*64];   // k-pair transposed

    {
        const float4* g1 = g_gw1p2 + (size_t)s*GW1_F4;
        for (int i=tid;i<GW1_F4;i+=T) s_gw1[i] = g1[i];
        const float* rw1s = g_rw1_t + (size_t)s*4096;
        for (int i=tid;i<4096;i+=T) s_rw1[i] = rw1s[i];
        const float* rw0s = rw0 + (size_t)s*768;
        for (int i=tid;i<768;i+=T) s_rw0[i] = rw0s[i];
        for (int i = tid; i < RMAX*64; i += T){ ((float*)sh_h0)[i] = 0.f; ((float*)sh_h1)[i] = 0.f; }
        if (tid < 128){
            sb_b1[0][tid] = b1[(s*2+0)*128 + tid];
            sb_b1[1][tid] = b1[(s*2+1)*128 + tid];
        }
        if (tid < 64){
            sb_ba[0][tid] = g_ba[(s*2+0)*64 + tid];
            sb_ba[1][tid] = g_ba[(s*2+1)*64 + tid];
            sb_b2[0][tid] = b2[(s*2+0)*64 + tid];
            sb_b2[1][tid] = b2[(s*2+1)*64 + tid];
            sb_rb1[tid]   = rb1[s*64 + tid];
        }
    }
    const float r_gb0f = gb0[s*256 + gm],     r_gb0i = gb0[s*256 + 64 + gm];
    const float r_gb0g = gb0[s*256 + 128+gm], r_gb0o = gb0[s*256 + 192 + gm];
    const float r_gb1f = gb1[s*256 + gm],     r_gb1i = gb1[s*256 + 64 + gm];
    const float r_gb1g = gb1[s*256 + 128+gm], r_gb1o = gb1[s*256 + 192 + gm];
    const float r_lag0 = lag[(s*2+0)*64+m],  r_lag1 = lag[(s*2+1)*64+m];
    const float r_lab0 = lab[(s*2+0)*64+m],  r_lab1 = lab[(s*2+1)*64+m];
    const float r_log0 = logw[(s*2+0)*64+m], r_log1 = logw[(s*2+1)*64+m];
    const float r_lob0 = lob[(s*2+0)*64+m],  r_lob1 = lob[(s*2+1)*64+m];
    const float r_rb0  = rb0[s*64+m];
    __syncthreads();

    // old-mapping rows (LN chain + inp): 4 groups x 3 rows
    int myr[3]; int nmy = 0;
    #pragma unroll
    for (int q=0;q<3;q++){ int r = rg + 4*q; myr[q] = (r < nrows) ? r : (nrows-1); if (r < nrows) nmy = q+1; }

    float c0s[3] = {0.f,0.f,0.f}, c1s[3] = {0.f,0.f,0.f};

    const float4* gw0g  = g_gw0p2 + (size_t)s*GW0_F4;
    const float4* Wa0_4 = (const float4*)g_Wa_t + (size_t)(s*2+0)*1024;
    const float4* Wa1_4 = (const float4*)g_Wa_t + (size_t)(s*2+1)*1024;
    const float4* w10_4 = (const float4*)g_w1_t + (size_t)(s*2+0)*2048;
    const float4* w11_4 = (const float4*)g_w1_t + (size_t)(s*2+1)*2048;
    const float4* w20_4 = (const float4*)g_w2_t + (size_t)(s*2+0)*2048;
    const float4* w21_4 = (const float4*)g_w2_t + (size_t)(s*2+1)*2048;

    const int Li  = (s==0) ? 170 : (s==1 ? 512 : 256);
    const int st0 = (s==0) ? 342 : (s==1 ? 0   : 256);
    const float scf = (float)Li / 512.0f;

    float* outbase = g_outs + ((size_t)s*512 + base)*512*64;

    auto ln_pass = [&](){
        for (int rr = wrp; rr < nrows; rr += 8){
            float va = sh_hy[rr][lane], vb = sh_hy[rr][lane+32];
            float sm = va + vb, sq = va*va + vb*vb;
            #pragma unroll
            for (int o=16;o;o>>=1){
                sm += __shfl_xor_sync(0xffffffffu, sm, o);
                sq += __shfl_xor_sync(0xffffffffu, sq, o);
            }
            if (lane == 0){
                float mean = sm * 0.015625f;
                float var  = sq * 0.015625f - mean*mean;
                sh_stat[rr][0] = mean;
                sh_stat[rr][1] = rsqrtf(var + 1e-5f);
            }
        }
    };
    auto ln_chain = [&](float (*hstate)[64], float* hn_out,
                        float lag_r, float lab_r, float log_r, float lob_r){
        ln_pass();
        __syncthreads();
        #pragma unroll
        for (int q=0;q<3;q++){
            int r = myr[q];
            float v  = sh_hy[r][m];
            float ln = (v - sh_stat[r][0]) * sh_stat[r][1] * lag_r + lab_r;
            float yv = ln + hstate[r][m];
            if (q < nmy) sh_hy[r][m] = yv;
        }
        __syncthreads();
        ln_pass();
        __syncthreads();
        #pragma unroll
        for (int q=0;q<3;q++){
            int r = myr[q];
            float yv = sh_hy[r][m];
            float hn = (yv - sh_stat[r][0]) * sh_stat[r][1] * log_r + lob_r;
            hn_out[q] = hn;
            if (q < nmy) hstate[r][m] = hn;
        }
    };

    // attn: 3 rows per warp (warps 0..3), full-warp weight cover
    auto attn_stage = [&](int l){
        if (sact){
            u64t a0[3], a1[3];
            #pragma unroll
            for (int j=0;j<3;j++){ a0[j] = pk2(sb_ba[l][sm2], 0.f); a1[j] = pk2(sb_ba[l][sm2+1], 0.f); }
            #pragma unroll 8
            for (int p=0;p<32;p++){
                ulonglong2 w = panu[p*32 + scp];
                #pragma unroll
                for (int j=0;j<3;j++){
                    u64t z = *(const u64t*)&sh_hy[srw[j]][2*p];
                    a0[j] = fma2(z, w.x, a0[j]);
                    a1[j] = fma2(z, w.y, a1[j]);
                }
            }
            #pragma unroll
            for (int j=0;j<3;j++)
                if (svr[j]) *(float2*)&sh_a[srw[j]][sm2] = make_float2(red2(a0[j]), red2(a1[j]));
        }
    };
    // ff1: all 8 warps, rows grow[], colpair gm
    auto ff1_stage = [&](int l){
        u64t t0[3], t1[3];
        #pragma unroll
        for (int j=0;j<3;j++){ t0[j] = pk2(sb_b1[l][fn2], 0.f); t1[j] = pk2(sb_b1[l][fn2+1], 0.f); }
        #pragma unroll 8
        for (int p=0;p<32;p++){
            ulonglong2 w = panu[p*64 + gm];
            #pragma unroll
            for (int j=0;j<3;j++){
                u64t z = *(const u64t*)&sh_a[grow[j]][2*p];
                t0[j] = fma2(z, w.x, t0[j]);
                t1[j] = fma2(z, w.y, t1[j]);
            }
        }
        const float c = 0.7071067811865475f;
        #pragma unroll
        for (int j=0;j<3;j++){
            float v0 = red2(t0[j]), v1 = red2(t1[j]);
            float g0 = 0.5f*v0*(1.0f + erff(v0*c));
            float g1 = 0.5f*v1*(1.0f + erff(v1*c));
            if (gvr[j]) *(float2*)&sh_t1[grow[j]][fn2] = make_float2(g0, g1);
        }
    };
    // ff2: warps 0..3, 3 rows, 64 k-pairs from sh_t1
    auto ff2_stage = [&](int l){
        if (sact){
            u64t a0[3], a1[3];
            #pragma unroll
            for (int j=0;j<3;j++){ a0[j] = pk2(sb_b2[l][sm2], 0.f); a1[j] = pk2(sb_b2[l][sm2+1], 0.f); }
            #pragma unroll 8
            for (int p=0;p<64;p++){
                ulonglong2 w = panu[p*32 + scp];
                #pragma unroll
                for (int j=0;j<3;j++){
                    u64t z = *(const u64t*)&sh_t1[srw[j]][2*p];
                    a0[j] = fma2(z, w.x, a0[j]);
                    a1[j] = fma2(z, w.y, a1[j]);
                }
            }
            #pragma unroll
            for (int j=0;j<3;j++)
                if (svr[j]) *(float2*)&sh_hy[srw[j]][sm2] = make_float2(red2(a0[j]), red2(a1[j]));
        }
    };

    for (int t=0; t<512; t++){
        cpyp<GW0_A>(pan4, gw0g, tid);
        {
            float srcf = fmaxf((t + 0.5f) * scf - 0.5f, 0.0f);
            int i0 = (int)srcf;
            if (i0 > Li-1) i0 = Li-1;
            int i1 = min(i0+1, Li-1);
            float wu = srcf - (float)i0;
            if (tid < nrows*12){
                int r = tid/12, k = tid%12;
                const float* xb = x + ((size_t)(base+r)*512 + st0)*12;
                float va = xb[i0*12 + k], vb = xb[i1*12 + k];
                sh_x[r][k] = va*(1.0f - wu) + vb*wu;
            }
        }
        __syncthreads();                              // S1: gw0A + sh_x ready

        // ---- gates layer 0 (f32x2, 3 rows/thread, redundancy 4) ----
        u64t aF[3], aI[3], aG[3], aO[3];
        #pragma unroll
        for (int j=0;j<3;j++){
            aF[j] = pk2(r_gb0f,0.f); aI[j] = pk2(r_gb0i,0.f);
            aG[j] = pk2(r_gb0g,0.f); aO[j] = pk2(r_gb0o,0.f);
        }
        #pragma unroll
        for (int p=0;p<6;p++){                        // k 0..11 from sh_x
            ulonglong2 wfi = panu[p*128 + gm], wgo = panu[p*128 + 64 + gm];
            #pragma unroll
            for (int j=0;j<3;j++){
                u64t z = *(const u64t*)&sh_x[grow[j]][2*p];
                aF[j] = fma2(z, wfi.x, aF[j]); aI[j] = fma2(z, wfi.y, aI[j]);
                aG[j] = fma2(z, wgo.x, aG[j]); aO[j] = fma2(z, wgo.y, aO[j]);
            }
        }
        #pragma unroll 7
        for (int p=6;p<20;p++){                       // k 12..39 from sh_h0
            ulonglong2 wfi = panu[p*128 + gm], wgo = panu[p*128 + 64 + gm];
            #pragma unroll
            for (int j=0;j<3;j++){
                u64t z = *(const u64t*)&sh_h0[grow[j]][2*p-12];
                aF[j] = fma2(z, wfi.x, aF[j]); aI[j] = fma2(z, wfi.y, aI[j]);
                aG[j] = fma2(z, wgo.x, aG[j]); aO[j] = fma2(z, wgo.y, aO[j]);
            }
        }
        __syncthreads();                              // S2: panel free
        cpyp<GW0_B>(pan4, gw0g + GW0_A, tid);
        __syncthreads();                              // S3: gw0B ready
        #pragma unroll 6
        for (int p=20;p<38;p++){                      // k 40..75 from sh_h0
            ulonglong2 wfi = panu[(p-20)*128 + gm], wgo = panu[(p-20)*128 + 64 + gm];
            #pragma unroll
            for (int j=0;j<3;j++){
                u64t z = *(const u64t*)&sh_h0[grow[j]][2*p-12];
                aF[j] = fma2(z, wfi.x, aF[j]); aI[j] = fma2(z, wfi.y, aI[j]);
                aG[j] = fma2(z, wgo.x, aG[j]); aO[j] = fma2(z, wgo.y, aO[j]);
            }
        }
        #pragma unroll
        for (int j=0;j<3;j++){
            float cn = sigmf(red2(aF[j]))*c0s[j] + sigmf(red2(aI[j]))*tanhfast(red2(aG[j]));
            float ht = sigmf(red2(aO[j]))*tanhfast(cn);
            if (gvr[j]){ c0s[j] = cn; sh_hy[grow[j]][gm] = ht; }
        }
        __syncthreads();                              // S4
        cpyp<1024>(pan4, Wa0_4, tid);
        __syncthreads();                              // S5
        attn_stage(0);
        __syncthreads();                              // S6
        cpyp<2048>(pan4, w10_4, tid);
        __syncthreads();                              // S7
        ff1_stage(0);
        __syncthreads();                              // S8
        cpyp<2048>(pan4, w20_4, tid);
        __syncthreads();                              // S9
        ff2_stage(0);
        __syncthreads();                              // S10
        float h0n[3];
        ln_chain(sh_h0, h0n, r_lag0, r_lab0, r_log0, r_lob0);
        #pragma unroll
        for (int q=0;q<3;q++){
            int r = myr[q];
            float acc = h0n[q] + r_rb0;
            #pragma unroll
            for (int k=0;k<12;k++) acc += sh_x[r][k] * s_rw0[k*64 + m];
            if (q < nmy) sh_inp[r][m] = acc;
        }
        __syncthreads();                              // S14
        cpyp<1024>(pan4, Wa1_4, tid);

        // ---- gates layer 1 (resident, f32x2, 3 rows/thread) ----
        u64t bF[3], bI[3], bG[3], bO[3];
        #pragma unroll
        for (int j=0;j<3;j++){
            bF[j] = pk2(r_gb1f,0.f); bI[j] = pk2(r_gb1i,0.f);
            bG[j] = pk2(r_gb1g,0.f); bO[j] = pk2(r_gb1o,0.f);
        }
        #pragma unroll 8
        for (int p=0;p<32;p++){                       // k 0..63 from sh_inp
            ulonglong2 wfi = gw1u[p*128 + gm], wgo = gw1u[p*128 + 64 + gm];
            #pragma unroll
            for (int j=0;j<3;j++){
                u64t z = *(const u64t*)&sh_inp[grow[j]][2*p];
                bF[j] = fma2(z, wfi.x, bF[j]); bI[j] = fma2(z, wfi.y, bI[j]);
                bG[j] = fma2(z, wgo.x, bG[j]); bO[j] = fma2(z, wgo.y, bO[j]);
            }
        }
        #pragma unroll 8
        for (int p=32;p<64;p++){                      // k 64..127 from sh_h1
            ulonglong2 wfi = gw1u[p*128 + gm], wgo = gw1u[p*128 + 64 + gm];
            #pragma unroll
            for (int j=0;j<3;j++){
                u64t z = *(const u64t*)&sh_h1[grow[j]][2*p-64];
                bF[j] = fma2(z, wfi.x, bF[j]); bI[j] = fma2(z, wfi.y, bI[j]);
                bG[j] = fma2(z, wgo.x, bG[j]); bO[j] = fma2(z, wgo.y, bO[j]);
            }
        }
        #pragma unroll
        for (int j=0;j<3;j++){
            float cn = sigmf(red2(bF[j]))*c1s[j] + sigmf(red2(bI[j]))*tanhfast(red2(bG[j]));
            float ht = sigmf(red2(bO[j]))*tanhfast(cn);
            if (gvr[j]){ c1s[j] = cn; sh_hy[grow[j]][gm] = ht; }
        }
        __syncthreads();                              // S15: Wa1 + hy ready
        attn_stage(1);
        __syncthreads();                              // S16
        cpyp<2048>(pan4, w11_4, tid);
        __syncthreads();                              // S17
        ff1_stage(1);
        __syncthreads();                              // S18
        cpyp<2048>(pan4, w21_4, tid);
        __syncthreads();                              // S19
        ff2_stage(1);
        __syncthreads();                              // S20
        float h1n[3];
        ln_chain(sh_h1, h1n, r_lag1, r_lab1, r_log1, r_lob1);
        __syncthreads();                              // S24

        // ---- out = h1 + inp@rw1 + rb1 (warps 0..3, 3 rows) ----
        if (sact){
            u64t a0[3], a1[3];
            #pragma unroll
            for (int j=0;j<3;j++){
                a0[j] = pk2(sb_rb1[sm2]   + sh_h1[srw[j]][sm2],   0.f);
                a1[j] = pk2(sb_rb1[sm2+1] + sh_h1[srw[j]][sm2+1], 0.f);
            }
            const ulonglong2* rwu = (const ulonglong2*)s_rw1;
            #pragma unroll 8
            for (int p=0;p<32;p++){
                ulonglong2 w = rwu[p*32 + scp];
                #pragma unroll
                for (int j=0;j<3;j++){
                    u64t z = *(const u64t*)&sh_inp[srw[j]][2*p];
                    a0[j] = fma2(z, w.x, a0[j]);
                    a1[j] = fma2(z, w.y, a1[j]);
                }
            }
            #pragma unroll
            for (int j=0;j<3;j++)
                if (svr[j]) ((float2*)(outbase + ((size_t)srw[j]*512 + t)*64))[scp] = make_float2(red2(a0[j]), red2(a1[j]));
        }
        __syncthreads();                              // S25
    }
}

__global__ void merge_kernel(const float* __restrict__ attn_w, float* __restrict__ out){
    int warp = (blockIdx.x*blockDim.x + threadIdx.x) >> 5;
    int lane = threadIdx.x & 31;
    if (warp >= 512*512) return;
    const size_t SS = 512ull*512*64;
    const float* p = g_outs + (size_t)warp*64;
    float aw0 = attn_w[lane], aw1 = attn_w[lane+32];
    float v0[3], v1[3], sc[3];
    #pragma unroll
    for (int si=0; si<3; si++){
        v0[si] = p[si*SS + lane];
        v1[si] = p[si*SS + lane + 32];
        float d = v0[si]*aw0 + v1[si]*aw1;
        #pragma unroll
        for (int o=16;o;o>>=1) d += __shfl_xor_sync(0xffffffffu, d, o);
        sc[si] = d;
    }
    float mx = fmaxf(sc[0], fmaxf(sc[1], sc[2]));
    float e0 = __expf(sc[0]-mx), e1 = __expf(sc[1]-mx), e2 = __expf(sc[2]-mx);
    float inv = __fdividef(1.0f, e0+e1+e2);
    float wt0 = e0*inv, wt1 = e1*inv, wt2 = e2*inv;
    out[(size_t)warp*64 + lane]      = v0[0]*wt0 + v0[1]*wt1 + v0[2]*wt2;
    out[(size_t)warp*64 + lane + 32] = v1[0]*wt0 + v1[1]*wt1 + v1[2]*wt2;
}

extern "C" void kernel_launch(void* const* d_in, const int* in_sizes, int n_in,
                              void* d_out, int out_size){
    const float* x     = (const float*)d_in[0];
    const float* gw0   = (const float*)d_in[1];
    const float* gb0   = (const float*)d_in[2];
    const float* gw1   = (const float*)d_in[3];
    const float* gb1   = (const float*)d_in[4];
    const float* mi_w  = (const float*)d_in[5];
    const float* mi_b  = (const float*)d_in[6];
    const float* mo_w  = (const float*)d_in[7];
    const float* mo_b  = (const float*)d_in[8];
    const float* w1    = (const float*)d_in[9];
    const float* b1    = (const float*)d_in[10];
    const float* w2    = (const float*)d_in[11];
    const float* b2    = (const float*)d_in[12];
    const float* lag   = (const float*)d_in[13];
    const float* lab   = (const float*)d_in[14];
    const float* logw  = (const float*)d_in[15];
    const float* lob   = (const float*)d_in[16];
    const float* rw0   = (const float*)d_in[17];
    const float* rb0   = (const float*)d_in[18];
    const float* rw1   = (const float*)d_in[19];
    const float* rb1   = (const float*)d_in[20];
    const float* attnw = (const float*)d_in[21];
    float* out = (float*)d_out;

    static int smem_set = 0;
    if (!smem_set){
        cudaFuncSetAttribute(xlstm_kernel, cudaFuncAttributeMaxDynamicSharedMemorySize, DYN_SMEM);
        smem_set = 1;
    }

    pack_gw_kernel<<<(3*128*256 + 255)/256, 256>>>(gw0, gw1);
    pack_t_kernel<<<(6*64*128 + 255)/256, 256>>>(w1, w2, rw1);
    compute_wa_kernel<<<6, 256>>>(mi_w, mi_b, mo_w, mo_b);
    xlstm_kernel<<<NCTA, T, DYN_SMEM>>>(x, gb0, gb1, b1, b2,
                                        lag, lab, logw, lob, rw0, rb0, rb1);
    merge_kernel<<<(512*512*32 + 255)/256, 256>>>(attnw, out);
}

// round 14
// speedup vs baseline: 1.3007x; 1.0130x over previous
#include <cuda_runtime.h>
#include <math.h>

#define NSC   48
#define RMAX  11
#define NCTA  (3*NSC)
#define T     256

#define GW0_F4 4864        // 38 pairs * 512B
#define GW0_A  2560        // pairs 0..19
#define GW0_B  2304        // pairs 20..37
#define GW1_F4 8192        // 64 pairs * 512B = 128KB
#define PAN_F4 2560        // 40KB panel
#define DYN_SMEM ((GW1_F4 + PAN_F4) * 16)   // 172,032 bytes

typedef unsigned long long u64t;

__device__ float4 g_gw0p2[3*GW0_F4];
__device__ float4 g_gw1p2[3*GW1_F4];
__device__ __align__(16) float g_Wa_t[6*4096];
__device__ __align__(16) float g_w1_t[6*8192];
__device__ __align__(16) float g_w2_t[6*8192];
__device__ __align__(16) float g_rw1_t[3*4096];
__device__ float g_ba[6*64];
__device__ float g_outs[3ull*512*512*64];

__device__ __forceinline__ float sigmf(float v){
    return __fdividef(1.0f, 1.0f + __expf(-v));
}
__device__ __forceinline__ float tanhfast(float v){
    return 1.0f - __fdividef(2.0f, __expf(2.0f*v) + 1.0f);
}
__device__ __forceinline__ u64t fma2(u64t a, u64t b, u64t c){
    u64t d;
    asm("fma.rn.f32x2 %0, %1, %2, %3;" : "=l"(d) : "l"(a), "l"(b), "l"(c));
    return d;
}
__device__ __forceinline__ u64t pk2(float lo, float hi){
    u64t r; asm("mov.b64 %0, {%1, %2};" : "=l"(r) : "f"(lo), "f"(hi)); return r;
}
__device__ __forceinline__ float red2(u64t v){
    float lo, hi; asm("mov.b64 {%0, %1}, %2;" : "=f"(lo), "=f"(hi) : "l"(v)); return lo + hi;
}

template<int N>
__device__ __forceinline__ void cpyp(float4* d, const float4* __restrict__ s, int tid){
    #pragma unroll
    for (int i = 0; i < (N + T - 1)/T; i++){
        int j = tid + i*T;
        if (j < N) d[j] = s[j];
    }
}

// ---- pack gates: per k-pair block: FI plane [64 x 16B] then GO plane [64 x 16B] ----
__global__ void pack_gw_kernel(const float* __restrict__ gw0, const float* __restrict__ gw1){
    int i = blockIdx.x*blockDim.x + threadIdx.x;
    float* p0 = (float*)g_gw0p2;
    float* p1 = (float*)g_gw1p2;
    if (i < 3*76*256){
        int s = i/(76*256), rem = i%(76*256), k = rem/256, j = rem%256;
        int g = j>>6, m = j&63, p = k>>1, h = k&1;
        int plane = g>>1;
        p0[(s*38 + p)*512 + plane*256 + m*4 + ((g&1)<<1) + h] = gw0[i];
    }
    if (i < 3*128*256){
        int s = i/(128*256), rem = i%(128*256), k = rem/256, j = rem%256;
        int g = j>>6, m = j&63, p = k>>1, h = k&1;
        int plane = g>>1;
        p1[(s*64 + p)*512 + plane*256 + m*4 + ((g&1)<<1) + h] = gw1[i];
    }
}

// ---- pack stage weights into [p][colpair][wk0c0,wk1c0,wk0c1,wk1c1] ----
__global__ void pack_t_kernel(const float* __restrict__ w1, const float* __restrict__ w2,
                              const float* __restrict__ rw1){
    int i = blockIdx.x*blockDim.x + threadIdx.x;
    if (i < 6*64*128){
        int sl = i/(64*128), k = (i/128)%64, n = i%128;
        g_w1_t[((sl*32 + (k>>1))*64 + (n>>1))*4 + ((n&1)<<1) + (k&1)] = w1[i];
    }
    if (i < 6*128*64){
        int sl = i/(128*64), k = (i/64)%128, n = i%64;
        g_w2_t[((sl*64 + (k>>1))*32 + (n>>1))*4 + ((n&1)<<1) + (k&1)] = w2[i];
    }
    if (i < 3*64*64){
        int s = i/(64*64), k = (i/64)%64, n = i%64;
        g_rw1_t[((s*32 + (k>>1))*32 + (n>>1))*4 + ((n&1)<<1) + (k&1)] = rw1[i];
    }
}

__global__ void compute_wa_kernel(const float* __restrict__ mi_w, const float* __restrict__ mi_b,
                                  const float* __restrict__ mo_w, const float* __restrict__ mo_b){
    int sl = blockIdx.x;
    const float* miw = mi_w + (size_t)sl*64*192;
    const float* mow = mo_w + (size_t)sl*64*64;
    for (int idx = threadIdx.x; idx < 64*64; idx += blockDim.x){
        int k = idx>>6, n = idx&63;
        float acc = 0.f;
        #pragma unroll 8
        for (int j=0;j<64;j++) acc += miw[k*192 + 128 + j] * mow[j*64 + n];
        g_Wa_t[((sl*32 + (k>>1))*32 + (n>>1))*4 + ((n&1)<<1) + (k&1)] = acc;
    }
    if (threadIdx.x < 64){
        int n = threadIdx.x;
        float acc = mo_b[sl*64 + n];
        #pragma unroll 8
        for (int j=0;j<64;j++) acc += mi_b[sl*192 + 128 + j] * mow[j*64 + n];
        g_ba[sl*64 + n] = acc;
    }
}

__global__ void __launch_bounds__(T, 1) xlstm_kernel(
    const float* __restrict__ x,
    const float* __restrict__ gb0, const float* __restrict__ gb1,
    const float* __restrict__ b1,  const float* __restrict__ b2,
    const float* __restrict__ lag, const float* __restrict__ lab,
    const float* __restrict__ logw,const float* __restrict__ lob,
    const float* __restrict__ rw0, const float* __restrict__ rb0,
    const float* __restrict__ rb1)
{
    const int cta = blockIdx.x;
    const int s   = cta / NSC;
    const int ci  = cta % NSC;
    const int base  = (ci < 32) ? ci*11 : 352 + (ci-32)*10;
    const int nrows = (ci < 32) ? 11 : 10;
    const int tid  = threadIdx.x;
    const int lane = tid & 31;
    const int wrp  = tid >> 5;          // 0..7

    // gates / ff1: 2 col-halves x 4 row-groups, 3 rows/thread
    const int colh = wrp & 1;
    const int rowg = wrp >> 1;          // 0..3
    const int gm   = colh*32 + lane;    // gate col / ff1 colpair
    const int fn2  = gm*2;
    int grow[3]; bool gvr[3];
    #pragma unroll
    for (int j=0;j<3;j++){ int r = rowg + 4*j; gvr[j] = (r < nrows); grow[j] = gvr[j] ? r : 0; }

    // attn / ff2+epilogue / out: 4 warps x 3 rows, lane = colpair
    const bool sact = (wrp < 4);
    const int scp   = lane;
    const int sm2   = lane*2;
    int srw[3]; bool svr[3];
    #pragma unroll
    for (int j=0;j<3;j++){ int r = wrp + 4*j; svr[j] = sact && (r < nrows); srw[j] = (r < nrows) ? r : 0; }

    extern __shared__ float4 dynsm[];
    float4* s_gw1 = dynsm;               // resident 128KB (plane-split pairs)
    float4* pan4  = dynsm + GW1_F4;      // 40KB panel
    const ulonglong2* gw1u = (const ulonglong2*)s_gw1;
    const ulonglong2* panu = (const ulonglong2*)pan4;

    __shared__ __align__(16) float sh_h0[RMAX][64], sh_h1[RMAX][64];
    __shared__ __align__(16) float sh_x[RMAX][12];
    __shared__ __align__(16) float sh_hy[RMAX][64];
    __shared__ __align__(16) float sh_a[RMAX][64];
    __shared__ __align__(16) float sh_t1[RMAX][128];
    __shared__ __align__(16) float sh_inp[RMAX][64];
    __shared__ __align__(16) float sb_ba[2][64];
    __shared__ __align__(16) float sb_b1[2][128];
    __shared__ __align__(16) float sb_b2[2][64];
    __shared__ __align__(16) float sb_rb1[64];
    __shared__ __align__(16) float s_rw0[12*64];
    __shared__ __align__(16) float s_rw1[64*64];   // k-pair transposed

    {
        const float4* g1 = g_gw1p2 + (size_t)s*GW1_F4;
        for (int i=tid;i<GW1_F4;i+=T) s_gw1[i] = g1[i];
        const float* rw1s = g_rw1_t + (size_t)s*4096;
        for (int i=tid;i<4096;i+=T) s_rw1[i] = rw1s[i];
        const float* rw0s = rw0 + (size_t)s*768;
        for (int i=tid;i<768;i+=T) s_rw0[i] = rw0s[i];
        for (int i = tid; i < RMAX*64; i += T){ ((float*)sh_h0)[i] = 0.f; ((float*)sh_h1)[i] = 0.f; }
        if (tid < 128){
            sb_b1[0][tid] = b1[(s*2+0)*128 + tid];
            sb_b1[1][tid] = b1[(s*2+1)*128 + tid];
        }
        if (tid < 64){
            sb_ba[0][tid] = g_ba[(s*2+0)*64 + tid];
            sb_ba[1][tid] = g_ba[(s*2+1)*64 + tid];
            sb_b2[0][tid] = b2[(s*2+0)*64 + tid];
            sb_b2[1][tid] = b2[(s*2+1)*64 + tid];
            sb_rb1[tid]   = rb1[s*64 + tid];
        }
    }
    // gate biases (col = gm)
    const float r_gb0f = gb0[s*256 + gm],     r_gb0i = gb0[s*256 + 64 + gm];
    const float r_gb0g = gb0[s*256 + 128+gm], r_gb0o = gb0[s*256 + 192 + gm];
    const float r_gb1f = gb1[s*256 + gm],     r_gb1i = gb1[s*256 + 64 + gm];
    const float r_gb1g = gb1[s*256 + 128+gm], r_gb1o = gb1[s*256 + 192 + gm];
    // LN params at epilogue cols (sm2, sm2+1), per layer
    const float lg0a = lag[(s*2+0)*64+sm2], lg0b = lag[(s*2+0)*64+sm2+1];
    const float lb0a = lab[(s*2+0)*64+sm2], lb0b = lab[(s*2+0)*64+sm2+1];
    const float lo0a = logw[(s*2+0)*64+sm2],lo0b = logw[(s*2+0)*64+sm2+1];
    const float lq0a = lob[(s*2+0)*64+sm2], lq0b = lob[(s*2+0)*64+sm2+1];
    const float lg1a = lag[(s*2+1)*64+sm2], lg1b = lag[(s*2+1)*64+sm2+1];
    const float lb1a = lab[(s*2+1)*64+sm2], lb1b = lab[(s*2+1)*64+sm2+1];
    const float lo1a = logw[(s*2+1)*64+sm2],lo1b = logw[(s*2+1)*64+sm2+1];
    const float lq1a = lob[(s*2+1)*64+sm2], lq1b = lob[(s*2+1)*64+sm2+1];
    const float r_rb0a = rb0[s*64+sm2], r_rb0b = rb0[s*64+sm2+1];
    __syncthreads();

    float c0s[3] = {0.f,0.f,0.f}, c1s[3] = {0.f,0.f,0.f};

    const float4* gw0g  = g_gw0p2 + (size_t)s*GW0_F4;
    const float4* Wa0_4 = (const float4*)g_Wa_t + (size_t)(s*2+0)*1024;
    const float4* Wa1_4 = (const float4*)g_Wa_t + (size_t)(s*2+1)*1024;
    const float4* w10_4 = (const float4*)g_w1_t + (size_t)(s*2+0)*2048;
    const float4* w11_4 = (const float4*)g_w1_t + (size_t)(s*2+1)*2048;
    const float4* w20_4 = (const float4*)g_w2_t + (size_t)(s*2+0)*2048;
    const float4* w21_4 = (const float4*)g_w2_t + (size_t)(s*2+1)*2048;

    const int Li  = (s==0) ? 170 : (s==1 ? 512 : 256);
    const int st0 = (s==0) ? 342 : (s==1 ? 0   : 256);
    const float scf = (float)Li / 512.0f;

    float* outbase = g_outs + ((size_t)s*512 + base)*512*64;

    // attn: 3 rows per warp (warps 0..3)
    auto attn_stage = [&](int l){
        if (sact){
            u64t a0[3], a1[3];
            #pragma unroll
            for (int j=0;j<3;j++){ a0[j] = pk2(sb_ba[l][sm2], 0.f); a1[j] = pk2(sb_ba[l][sm2+1], 0.f); }
            #pragma unroll 8
            for (int p=0;p<32;p++){
                ulonglong2 w = panu[p*32 + scp];
                #pragma unroll
                for (int j=0;j<3;j++){
                    u64t z = *(const u64t*)&sh_hy[srw[j]][2*p];
                    a0[j] = fma2(z, w.x, a0[j]);
                    a1[j] = fma2(z, w.y, a1[j]);
                }
            }
            #pragma unroll
            for (int j=0;j<3;j++)
                if (svr[j]) *(float2*)&sh_a[srw[j]][sm2] = make_float2(red2(a0[j]), red2(a1[j]));
        }
    };
    // ff1: all 8 warps
    auto ff1_stage = [&](int l){
        u64t t0[3], t1[3];
        #pragma unroll
        for (int j=0;j<3;j++){ t0[j] = pk2(sb_b1[l][fn2], 0.f); t1[j] = pk2(sb_b1[l][fn2+1], 0.f); }
        #pragma unroll 8
        for (int p=0;p<32;p++){
            ulonglong2 w = panu[p*64 + gm];
            #pragma unroll
            for (int j=0;j<3;j++){
                u64t z = *(const u64t*)&sh_a[grow[j]][2*p];
                t0[j] = fma2(z, w.x, t0[j]);
                t1[j] = fma2(z, w.y, t1[j]);
            }
        }
        const float c = 0.7071067811865475f;
        #pragma unroll
        for (int j=0;j<3;j++){
            float v0 = red2(t0[j]), v1 = red2(t1[j]);
            float g0 = 0.5f*v0*(1.0f + erff(v0*c));
            float g1 = 0.5f*v1*(1.0f + erff(v1*c));
            if (gvr[j]) *(float2*)&sh_t1[grow[j]][fn2] = make_float2(g0, g1);
        }
    };

    // ff2 + in-register LN chain + (inp | out) epilogue; warps 0..3 only
    auto ff2_epi = [&](int l, float (*hstate)[64],
                       float lgA, float lgB, float lbA, float lbB,
                       float loA, float loB, float lqA, float lqB,
                       bool layer0, int t){
        if (!sact) return;
        u64t a0[3], a1[3];
        #pragma unroll
        for (int j=0;j<3;j++){ a0[j] = pk2(sb_b2[l][sm2], 0.f); a1[j] = pk2(sb_b2[l][sm2+1], 0.f); }
        #pragma unroll 8
        for (int p=0;p<64;p++){
            ulonglong2 w = panu[p*32 + scp];
            #pragma unroll
            for (int j=0;j<3;j++){
                u64t z = *(const u64t*)&sh_t1[srw[j]][2*p];
                a0[j] = fma2(z, w.x, a0[j]);
                a1[j] = fma2(z, w.y, a1[j]);
            }
        }
        #pragma unroll
        for (int j=0;j<3;j++){
            float y0 = red2(a0[j]), y1 = red2(a1[j]);
            // LN1 (row across warp: lane holds cols sm2, sm2+1)
            float sm = y0 + y1, sq = y0*y0 + y1*y1;
            #pragma unroll
            for (int o=16;o;o>>=1){
                sm += __shfl_xor_sync(0xffffffffu, sm, o);
                sq += __shfl_xor_sync(0xffffffffu, sq, o);
            }
            float mean = sm * 0.015625f;
            float rstd = rsqrtf(sq*0.015625f - mean*mean + 1e-5f);
            float2 hv = *(const float2*)&hstate[srw[j]][sm2];
            float z0 = (y0 - mean)*rstd*lgA + lbA + hv.x;
            float z1 = (y1 - mean)*rstd*lgB + lbB + hv.y;
            // LN2
            float sm2_ = z0 + z1, sq2 = z0*z0 + z1*z1;
            #pragma unroll
            for (int o=16;o;o>>=1){
                sm2_ += __shfl_xor_sync(0xffffffffu, sm2_, o);
                sq2  += __shfl_xor_sync(0xffffffffu, sq2,  o);
            }
            float mean2 = sm2_ * 0.015625f;
            float rstd2 = rsqrtf(sq2*0.015625f - mean2*mean2 + 1e-5f);
            float h0 = (z0 - mean2)*rstd2*loA + lqA;
            float h1 = (z1 - mean2)*rstd2*loB + lqB;
            if (svr[j]) *(float2*)&hstate[srw[j]][sm2] = make_float2(h0, h1);
            if (layer0){
                // inp = h0_new + x @ rw0 + rb0
                float i0 = h0 + r_rb0a, i1 = h1 + r_rb0b;
                #pragma unroll
                for (int k=0;k<12;k++){
                    float xv = sh_x[srw[j]][k];
                    float2 wv = *(const float2*)&s_rw0[k*64 + sm2];
                    i0 = fmaf(xv, wv.x, i0);
                    i1 = fmaf(xv, wv.y, i1);
                }
                if (svr[j]) *(float2*)&sh_inp[srw[j]][sm2] = make_float2(i0, i1);
            } else {
                // out = h1_new + inp @ rw1 + rb1
                u64t oa = pk2(h0 + sb_rb1[sm2],   0.f);
                u64t ob = pk2(h1 + sb_rb1[sm2+1], 0.f);
                const ulonglong2* rwu = (const ulonglong2*)s_rw1;
                #pragma unroll 8
                for (int p=0;p<32;p++){
                    ulonglong2 w = rwu[p*32 + scp];
                    u64t z = *(const u64t*)&sh_inp[srw[j]][2*p];
                    oa = fma2(z, w.x, oa);
                    ob = fma2(z, w.y, ob);
                }
                if (svr[j]) ((float2*)(outbase + ((size_t)srw[j]*512 + t)*64))[scp] = make_float2(red2(oa), red2(ob));
            }
        }
    };

    for (int t=0; t<512; t++){
        cpyp<GW0_A>(pan4, gw0g, tid);
        {
            float srcf = fmaxf((t + 0.5f) * scf - 0.5f, 0.0f);
            int i0 = (int)srcf;
            if (i0 > Li-1) i0 = Li-1;
            int i1 = min(i0+1, Li-1);
            float wu = srcf - (float)i0;
            if (tid < nrows*12){
                int r = tid/12, k = tid%12;
                const float* xb = x + ((size_t)(base+r)*512 + st0)*12;
                float va = xb[i0*12 + k], vb = xb[i1*12 + k];
                sh_x[r][k] = va*(1.0f - wu) + vb*wu;
            }
        }
        __syncthreads();                              // S1: gw0A + sh_x ready

        // ---- gates layer 0 (f32x2, 3 rows/thread) ----
        u64t aF[3], aI[3], aG[3], aO[3];
        #pragma unroll
        for (int j=0;j<3;j++){
            aF[j] = pk2(r_gb0f,0.f); aI[j] = pk2(r_gb0i,0.f);
            aG[j] = pk2(r_gb0g,0.f); aO[j] = pk2(r_gb0o,0.f);
        }
        #pragma unroll
        for (int p=0;p<6;p++){                        // k 0..11 from sh_x
            ulonglong2 wfi = panu[p*128 + gm], wgo = panu[p*128 + 64 + gm];
            #pragma unroll
            for (int j=0;j<3;j++){
                u64t z = *(const u64t*)&sh_x[grow[j]][2*p];
                aF[j] = fma2(z, wfi.x, aF[j]); aI[j] = fma2(z, wfi.y, aI[j]);
                aG[j] = fma2(z, wgo.x, aG[j]); aO[j] = fma2(z, wgo.y, aO[j]);
            }
        }
        #pragma unroll 7
        for (int p=6;p<20;p++){                       // k 12..39 from sh_h0
            ulonglong2 wfi = panu[p*128 + gm], wgo = panu[p*128 + 64 + gm];
            #pragma unroll
            for (int j=0;j<3;j++){
                u64t z = *(const u64t*)&sh_h0[grow[j]][2*p-12];
                aF[j] = fma2(z, wfi.x, aF[j]); aI[j] = fma2(z, wfi.y, aI[j]);
                aG[j] = fma2(z, wgo.x, aG[j]); aO[j] = fma2(z, wgo.y, aO[j]);
            }
        }
        __syncthreads();                              // S2: panel free
        cpyp<GW0_B>(pan4, gw0g + GW0_A, tid);
        __syncthreads();                              // S3: gw0B ready
        #pragma unroll 6
        for (int p=20;p<38;p++){                      // k 40..75 from sh_h0
            ulonglong2 wfi = panu[(p-20)*128 + gm], wgo = panu[(p-20)*128 + 64 + gm];
            #pragma unroll
            for (int j=0;j<3;j++){
                u64t z = *(const u64t*)&sh_h0[grow[j]][2*p-12];
                aF[j] = fma2(z, wfi.x, aF[j]); aI[j] = fma2(z, wfi.y, aI[j]);
                aG[j] = fma2(z, wgo.x, aG[j]); aO[j] = fma2(z, wgo.y, aO[j]);
            }
        }
        #pragma unroll
        for (int j=0;j<3;j++){
            float cn = sigmf(red2(aF[j]))*c0s[j] + sigmf(red2(aI[j]))*tanhfast(red2(aG[j]));
            float ht = sigmf(red2(aO[j]))*tanhfast(cn);
            if (gvr[j]){ c0s[j] = cn; sh_hy[grow[j]][gm] = ht; }
        }
        __syncthreads();                              // S4: hy ready, panel free
        cpyp<1024>(pan4, Wa0_4, tid);
        __syncthreads();                              // S5
        attn_stage(0);
        __syncthreads();                              // S6
        cpyp<2048>(pan4, w10_4, tid);
        __syncthreads();                              // S7
        ff1_stage(0);
        __syncthreads();                              // S8
        cpyp<2048>(pan4, w20_4, tid);
        __syncthreads();                              // S9
        ff2_epi(0, sh_h0, lg0a, lg0b, lb0a, lb0b, lo0a, lo0b, lq0a, lq0b, true, t);
        __syncthreads();                              // S10: sh_inp + sh_h0 ready, panel free
        cpyp<1024>(pan4, Wa1_4, tid);

        // ---- gates layer 1 (resident, f32x2, 3 rows/thread) ----
        u64t bF[3], bI[3], bG[3], bO[3];
        #pragma unroll
        for (int j=0;j<3;j++){
            bF[j] = pk2(r_gb1f,0.f); bI[j] = pk2(r_gb1i,0.f);
            bG[j] = pk2(r_gb1g,0.f); bO[j] = pk2(r_gb1o,0.f);
        }
        #pragma unroll 8
        for (int p=0;p<32;p++){                       // k 0..63 from sh_inp
            ulonglong2 wfi = gw1u[p*128 + gm], wgo = gw1u[p*128 + 64 + gm];
            #pragma unroll
            for (int j=0;j<3;j++){
                u64t z = *(const u64t*)&sh_inp[grow[j]][2*p];
                bF[j] = fma2(z, wfi.x, bF[j]); bI[j] = fma2(z, wfi.y, bI[j]);
                bG[j] = fma2(z, wgo.x, bG[j]); bO[j] = fma2(z, wgo.y, bO[j]);
            }
        }
        #pragma unroll 8
        for (int p=32;p<64;p++){                      // k 64..127 from sh_h1
            ulonglong2 wfi = gw1u[p*128 + gm], wgo = gw1u[p*128 + 64 + gm];
            #pragma unroll
            for (int j=0;j<3;j++){
                u64t z = *(const u64t*)&sh_h1[grow[j]][2*p-64];
                bF[j] = fma2(z, wfi.x, bF[j]); bI[j] = fma2(z, wfi.y, bI[j]);
                bG[j] = fma2(z, wgo.x, bG[j]); bO[j] = fma2(z, wgo.y, bO[j]);
            }
        }
        #pragma unroll
        for (int j=0;j<3;j++){
            float cn = sigmf(red2(bF[j]))*c1s[j] + sigmf(red2(bI[j]))*tanhfast(red2(bG[j]));
            float ht = sigmf(red2(bO[j]))*tanhfast(cn);
            if (gvr[j]){ c1s[j] = cn; sh_hy[grow[j]][gm] = ht; }
        }
        __syncthreads();                              // S11: Wa1 + hy ready
        attn_stage(1);
        __syncthreads();                              // S12
        cpyp<2048>(pan4, w11_4, tid);
        __syncthreads();                              // S13
        ff1_stage(1);
        __syncthreads();                              // S14
        cpyp<2048>(pan4, w21_4, tid);
        __syncthreads();                              // S15
        ff2_epi(1, sh_h1, lg1a, lg1b, lb1a, lb1b, lo1a, lo1b, lq1a, lq1b, false, t);
        __syncthreads();                              // S16: sh_h1 ready, panel free
    }
}

__global__ void merge_kernel(const float* __restrict__ attn_w, float* __restrict__ out){
    int warp = (blockIdx.x*blockDim.x + threadIdx.x) >> 5;
    int lane = threadIdx.x & 31;
    if (warp >= 512*512) return;
    const size_t SS = 512ull*512*64;
    const float* p = g_outs + (size_t)warp*64;
    float aw0 = attn_w[lane], aw1 = attn_w[lane+32];
    float v0[3], v1[3], sc[3];
    #pragma unroll
    for (int si=0; si<3; si++){
        v0[si] = p[si*SS + lane];
        v1[si] = p[si*SS + lane + 32];
        float d = v0[si]*aw0 + v1[si]*aw1;
        #pragma unroll
        for (int o=16;o;o>>=1) d += __shfl_xor_sync(0xffffffffu, d, o);
        sc[si] = d;
    }
    float mx = fmaxf(sc[0], fmaxf(sc[1], sc[2]));
    float e0 = __expf(sc[0]-mx), e1 = __expf(sc[1]-mx), e2 = __expf(sc[2]-mx);
    float inv = __fdividef(1.0f, e0+e1+e2);
    float wt0 = e0*inv, wt1 = e1*inv, wt2 = e2*inv;
    out[(size_t)warp*64 + lane]      = v0[0]*wt0 + v0[1]*wt1 + v0[2]*wt2;
    out[(size_t)warp*64 + lane + 32] = v1[0]*wt0 + v1[1]*wt1 + v1[2]*wt2;
}

extern "C" void kernel_launch(void* const* d_in, const int* in_sizes, int n_in,
                              void* d_out, int out_size){
    const float* x     = (const float*)d_in[0];
    const float* gw0   = (const float*)d_in[1];
    const float* gb0   = (const float*)d_in[2];
    const float* gw1   = (const float*)d_in[3];
    const float* gb1   = (const float*)d_in[4];
    const float* mi_w  = (const float*)d_in[5];
    const float* mi_b  = (const float*)d_in[6];
    const float* mo_w  = (const float*)d_in[7];
    const float* mo_b  = (const float*)d_in[8];
    const float* w1    = (const float*)d_in[9];
    const float* b1    = (const float*)d_in[10];
    const float* w2    = (const float*)d_in[11];
    const float* b2    = (const float*)d_in[12];
    const float* lag   = (const float*)d_in[13];
    const float* lab   = (const float*)d_in[14];
    const float* logw  = (const float*)d_in[15];
    const float* lob   = (const float*)d_in[16];
    const float* rw0   = (const float*)d_in[17];
    const float* rb0   = (const float*)d_in[18];
    const float* rw1   = (const float*)d_in[19];
    const float* rb1   = (const float*)d_in[20];
    const float* attnw = (const float*)d_in[21];
    float* out = (float*)d_out;

    static int smem_set = 0;
    if (!smem_set){
        cudaFuncSetAttribute(xlstm_kernel, cudaFuncAttributeMaxDynamicSharedMemorySize, DYN_SMEM);
        smem_set = 1;
    }

    pack_gw_kernel<<<(3*128*256 + 255)/256, 256>>>(gw0, gw1);
    pack_t_kernel<<<(6*64*128 + 255)/256, 256>>>(w1, w2, rw1);
    compute_wa_kernel<<<6, 256>>>(mi_w, mi_b, mo_w, mo_b);
    xlstm_kernel<<<NCTA, T, DYN_SMEM>>>(x, gb0, gb1, b1, b2,
                                        lag, lab, logw, lob, rw0, rb0, rb1);
    merge_kernel<<<(512*512*32 + 255)/256, 256>>>(attnw, out);
}

// round 15
// speedup vs baseline: 1.3009x; 1.0001x over previous
#include <cuda_runtime.h>
#include <math.h>

#define NSC   48
#define RMAX  11
#define NCTA  (3*NSC)
#define T     256

// dynamic smem layout (float4 units):
//  [0,6144)      gw1 resident pairs 0..47
//  [6144,7168)   rw1 transposed
//  [7168,9216)   B1 panel (2048)
//  [9216,11264)  B2 panel (2048)
//  [11264,12288) S  panel (1024)
#define GW1_RES 6144
#define RW1_OFF 6144
#define B1_OFF  7168
#define B2_OFF  9216
#define S_OFF   11264
#define DYN_SMEM (12288*16)   // 196,608 B

typedef unsigned long long u64t;

__device__ float4 g_gw0p2[3*4864];
__device__ float4 g_gw1p2[3*8192];
__device__ __align__(16) float g_Wa_t[6*4096];
__device__ __align__(16) float g_w1_t[6*8192];
__device__ __align__(16) float g_w2_t[6*8192];
__device__ __align__(16) float g_rw1_t[3*4096];
__device__ float g_ba[6*64];
__device__ float g_outs[3ull*512*512*64];

__device__ __forceinline__ float sigmf(float v){
    return __fdividef(1.0f, 1.0f + __expf(-v));
}
__device__ __forceinline__ float tanhfast(float v){
    return 1.0f - __fdividef(2.0f, __expf(2.0f*v) + 1.0f);
}
__device__ __forceinline__ u64t fma2(u64t a, u64t b, u64t c){
    u64t d;
    asm("fma.rn.f32x2 %0, %1, %2, %3;" : "=l"(d) : "l"(a), "l"(b), "l"(c));
    return d;
}
__device__ __forceinline__ u64t pk2(float lo, float hi){
    u64t r; asm("mov.b64 %0, {%1, %2};" : "=l"(r) : "f"(lo), "f"(hi)); return r;
}
__device__ __forceinline__ float red2(u64t v){
    float lo, hi; asm("mov.b64 {%0, %1}, %2;" : "=f"(lo), "=f"(hi) : "l"(v)); return lo + hi;
}

template<int N>
__device__ __forceinline__ void cpyp(float4* d, const float4* __restrict__ s, int tid){
    #pragma unroll
    for (int i = 0; i < (N + T - 1)/T; i++){
        int j = tid + i*T;
        if (j < N) d[j] = s[j];
    }
}

// ---- pack gates: per k-pair block: FI plane [64 x 16B] then GO plane [64 x 16B] ----
__global__ void pack_gw_kernel(const float* __restrict__ gw0, const float* __restrict__ gw1){
    int i = blockIdx.x*blockDim.x + threadIdx.x;
    float* p0 = (float*)g_gw0p2;
    float* p1 = (float*)g_gw1p2;
    if (i < 3*76*256){
        int s = i/(76*256), rem = i%(76*256), k = rem/256, j = rem%256;
        int g = j>>6, m = j&63, p = k>>1, h = k&1;
        int plane = g>>1;
        p0[(s*38 + p)*512 + plane*256 + m*4 + ((g&1)<<1) + h] = gw0[i];
    }
    if (i < 3*128*256){
        int s = i/(128*256), rem = i%(128*256), k = rem/256, j = rem%256;
        int g = j>>6, m = j&63, p = k>>1, h = k&1;
        int plane = g>>1;
        p1[(s*64 + p)*512 + plane*256 + m*4 + ((g&1)<<1) + h] = gw1[i];
    }
}

// ---- pack stage weights into [p][colpair][wk0c0,wk1c0,wk0c1,wk1c1] ----
__global__ void pack_t_kernel(const float* __restrict__ w1, const float* __restrict__ w2,
                              const float* __restrict__ rw1){
    int i = blockIdx.x*blockDim.x + threadIdx.x;
    if (i < 6*64*128){
        int sl = i/(64*128), k = (i/128)%64, n = i%128;
        g_w1_t[((sl*32 + (k>>1))*64 + (n>>1))*4 + ((n&1)<<1) + (k&1)] = w1[i];
    }
    if (i < 6*128*64){
        int sl = i/(128*64), k = (i/64)%128, n = i%64;
        g_w2_t[((sl*64 + (k>>1))*32 + (n>>1))*4 + ((n&1)<<1) + (k&1)] = w2[i];
    }
    if (i < 3*64*64){
        int s = i/(64*64), k = (i/64)%64, n = i%64;
        g_rw1_t[((s*32 + (k>>1))*32 + (n>>1))*4 + ((n&1)<<1) + (k&1)] = rw1[i];
    }
}

__global__ void compute_wa_kernel(const float* __restrict__ mi_w, const float* __restrict__ mi_b,
                                  const float* __restrict__ mo_w, const float* __restrict__ mo_b){
    int sl = blockIdx.x;
    const float* miw = mi_w + (size_t)sl*64*192;
    const float* mow = mo_w + (size_t)sl*64*64;
    for (int idx = threadIdx.x; idx < 64*64; idx += blockDim.x){
        int k = idx>>6, n = idx&63;
        float acc = 0.f;
        #pragma unroll 8
        for (int j=0;j<64;j++) acc += miw[k*192 + 128 + j] * mow[j*64 + n];
        g_Wa_t[((sl*32 + (k>>1))*32 + (n>>1))*4 + ((n&1)<<1) + (k&1)] = acc;
    }
    if (threadIdx.x < 64){
        int n = threadIdx.x;
        float acc = mo_b[sl*64 + n];
        #pragma unroll 8
        for (int j=0;j<64;j++) acc += mi_b[sl*192 + 128 + j] * mow[j*64 + n];
        g_ba[sl*64 + n] = acc;
    }
}

__global__ void __launch_bounds__(T, 1) xlstm_kernel(
    const float* __restrict__ x,
    const float* __restrict__ gb0, const float* __restrict__ gb1,
    const float* __restrict__ b1,  const float* __restrict__ b2,
    const float* __restrict__ lag, const float* __restrict__ lab,
    const float* __restrict__ logw,const float* __restrict__ lob,
    const float* __restrict__ rw0, const float* __restrict__ rb0,
    const float* __restrict__ rb1)
{
    const int cta = blockIdx.x;
    const int s   = cta / NSC;
    const int ci  = cta % NSC;
    const int base  = (ci < 32) ? ci*11 : 352 + (ci-32)*10;
    const int nrows = (ci < 32) ? 11 : 10;
    const int tid  = threadIdx.x;
    const int lane = tid & 31;
    const int wrp  = tid >> 5;          // 0..7

    // gates / ff1: 2 col-halves x 4 row-groups, 3 rows/thread
    const int colh = wrp & 1;
    const int rowg = wrp >> 1;          // 0..3
    const int gm   = colh*32 + lane;    // gate col / ff1 colpair
    const int fn2  = gm*2;
    int grow[3]; bool gvr[3];
    #pragma unroll
    for (int j=0;j<3;j++){ int r = rowg + 4*j; gvr[j] = (r < nrows); grow[j] = gvr[j] ? r : 0; }

    // attn / ff2+epilogue / out: 4 warps x 3 rows, lane = colpair
    const bool sact = (wrp < 4);
    const int scp   = lane;
    const int sm2   = lane*2;
    int srw[3]; bool svr[3];
    #pragma unroll
    for (int j=0;j<3;j++){ int r = wrp + 4*j; svr[j] = sact && (r < nrows); srw[j] = (r < nrows) ? r : 0; }

    extern __shared__ float4 dynsm[];
    float4* B1 = dynsm + B1_OFF;
    float4* B2 = dynsm + B2_OFF;
    float4* Sp = dynsm + S_OFF;
    const ulonglong2* gw1u = (const ulonglong2*)dynsm;            // resident pairs 0..47
    const ulonglong2* rwu  = (const ulonglong2*)(dynsm + RW1_OFF);
    const ulonglong2* B1u  = (const ulonglong2*)B1;
    const ulonglong2* B2u  = (const ulonglong2*)B2;
    const ulonglong2* Su   = (const ulonglong2*)Sp;

    __shared__ __align__(16) float sh_h0[RMAX][64], sh_h1[RMAX][64];
    __shared__ __align__(16) float sh_x[2][RMAX][12];
    __shared__ __align__(16) float sh_hy[RMAX][64];
    __shared__ __align__(16) float sh_a[RMAX][64];
    __shared__ __align__(16) float sh_t1[RMAX][128];
    __shared__ __align__(16) float sh_inp[RMAX][64];
    __shared__ __align__(16) float sb_ba[2][64];
    __shared__ __align__(16) float sb_b1[2][128];
    __shared__ __align__(16) float sb_b2[2][64];
    __shared__ __align__(16) float sb_rb1[64];
    __shared__ __align__(16) float s_rw0[12*64];

    const float4* gw0g = g_gw0p2 + (size_t)s*4864;
    const float4* gw1g = g_gw1p2 + (size_t)s*8192;
    const float4* Wa0_4 = (const float4*)g_Wa_t + (size_t)(s*2+0)*1024;
    const float4* Wa1_4 = (const float4*)g_Wa_t + (size_t)(s*2+1)*1024;
    const float4* w10_4 = (const float4*)g_w1_t + (size_t)(s*2+0)*2048;
    const float4* w11_4 = (const float4*)g_w1_t + (size_t)(s*2+1)*2048;
    const float4* w20_4 = (const float4*)g_w2_t + (size_t)(s*2+0)*2048;
    const float4* w21_4 = (const float4*)g_w2_t + (size_t)(s*2+1)*2048;

    const int Li  = (s==0) ? 170 : (s==1 ? 512 : 256);
    const int st0 = (s==0) ? 342 : (s==1 ? 0   : 256);
    const float scf = (float)Li / 512.0f;

    auto xups = [&](int tt, float (*xbuf)[12]){
        float srcf = fmaxf((tt + 0.5f) * scf - 0.5f, 0.0f);
        int i0 = (int)srcf;
        if (i0 > Li-1) i0 = Li-1;
        int i1 = min(i0+1, Li-1);
        float wu = srcf - (float)i0;
        if (tid < nrows*12){
            int r = tid/12, k = tid%12;
            const float* xb = x + ((size_t)(base+r)*512 + st0)*12;
            float va = xb[i0*12 + k], vb = xb[i1*12 + k];
            xbuf[r][k] = va*(1.0f - wu) + vb*wu;
        }
    };

    // ---- prologue: resident loads + first panel + x(t=0) ----
    {
        for (int i=tid;i<GW1_RES;i+=T) dynsm[i] = gw1g[i];               // gw1 pairs 0..47
        const float4* rw1s = (const float4*)g_rw1_t + (size_t)s*1024;
        for (int i=tid;i<1024;i+=T) dynsm[RW1_OFF + i] = rw1s[i];
        const float* rw0s = rw0 + (size_t)s*768;
        for (int i=tid;i<768;i+=T) s_rw0[i] = rw0s[i];
        for (int i = tid; i < RMAX*64; i += T){ ((float*)sh_h0)[i] = 0.f; ((float*)sh_h1)[i] = 0.f; }
        if (tid < 128){
            sb_b1[0][tid] = b1[(s*2+0)*128 + tid];
            sb_b1[1][tid] = b1[(s*2+1)*128 + tid];
        }
        if (tid < 64){
            sb_ba[0][tid] = g_ba[(s*2+0)*64 + tid];
            sb_ba[1][tid] = g_ba[(s*2+1)*64 + tid];
            sb_b2[0][tid] = b2[(s*2+0)*64 + tid];
            sb_b2[1][tid] = b2[(s*2+1)*64 + tid];
            sb_rb1[tid]   = rb1[s*64 + tid];
        }
        cpyp<2048>(B1, gw0g, tid);      // gw0 pairs 0..15
        xups(0, sh_x[0]);
    }
    const float r_gb0f = gb0[s*256 + gm],     r_gb0i = gb0[s*256 + 64 + gm];
    const float r_gb0g = gb0[s*256 + 128+gm], r_gb0o = gb0[s*256 + 192 + gm];
    const float r_gb1f = gb1[s*256 + gm],     r_gb1i = gb1[s*256 + 64 + gm];
    const float r_gb1g = gb1[s*256 + 128+gm], r_gb1o = gb1[s*256 + 192 + gm];
    const float lg0a = lag[(s*2+0)*64+sm2], lg0b = lag[(s*2+0)*64+sm2+1];
    const float lb0a = lab[(s*2+0)*64+sm2], lb0b = lab[(s*2+0)*64+sm2+1];
    const float lo0a = logw[(s*2+0)*64+sm2],lo0b = logw[(s*2+0)*64+sm2+1];
    const float lq0a = lob[(s*2+0)*64+sm2], lq0b = lob[(s*2+0)*64+sm2+1];
    const float lg1a = lag[(s*2+1)*64+sm2], lg1b = lag[(s*2+1)*64+sm2+1];
    const float lb1a = lab[(s*2+1)*64+sm2], lb1b = lab[(s*2+1)*64+sm2+1];
    const float lo1a = logw[(s*2+1)*64+sm2],lo1b = logw[(s*2+1)*64+sm2+1];
    const float lq1a = lob[(s*2+1)*64+sm2], lq1b = lob[(s*2+1)*64+sm2+1];
    const float r_rb0a = rb0[s*64+sm2], r_rb0b = rb0[s*64+sm2+1];
    __syncthreads();

    float c0s[3] = {0.f,0.f,0.f}, c1s[3] = {0.f,0.f,0.f};
    float* outbase = g_outs + ((size_t)s*512 + base)*512*64;

    auto attn_stage = [&](int l, const ulonglong2* wp){
        if (sact){
            u64t a0[3], a1[3];
            #pragma unroll
            for (int j=0;j<3;j++){ a0[j] = pk2(sb_ba[l][sm2], 0.f); a1[j] = pk2(sb_ba[l][sm2+1], 0.f); }
            #pragma unroll 8
            for (int p=0;p<32;p++){
                ulonglong2 w = wp[p*32 + scp];
                #pragma unroll
                for (int j=0;j<3;j++){
                    u64t z = *(const u64t*)&sh_hy[srw[j]][2*p];
                    a0[j] = fma2(z, w.x, a0[j]);
                    a1[j] = fma2(z, w.y, a1[j]);
                }
            }
            #pragma unroll
            for (int j=0;j<3;j++)
                if (svr[j]) *(float2*)&sh_a[srw[j]][sm2] = make_float2(red2(a0[j]), red2(a1[j]));
        }
    };
    auto ff1_stage = [&](int l, const ulonglong2* wp){
        u64t t0[3], t1[3];
        #pragma unroll
        for (int j=0;j<3;j++){ t0[j] = pk2(sb_b1[l][fn2], 0.f); t1[j] = pk2(sb_b1[l][fn2+1], 0.f); }
        #pragma unroll 8
        for (int p=0;p<32;p++){
            ulonglong2 w = wp[p*64 + gm];
            #pragma unroll
            for (int j=0;j<3;j++){
                u64t z = *(const u64t*)&sh_a[grow[j]][2*p];
                t0[j] = fma2(z, w.x, t0[j]);
                t1[j] = fma2(z, w.y, t1[j]);
            }
        }
        const float c = 0.7071067811865475f;
        #pragma unroll
        for (int j=0;j<3;j++){
            float v0 = red2(t0[j]), v1 = red2(t1[j]);
            float g0 = 0.5f*v0*(1.0f + erff(v0*c));
            float g1 = 0.5f*v1*(1.0f + erff(v1*c));
            if (gvr[j]) *(float2*)&sh_t1[grow[j]][fn2] = make_float2(g0, g1);
        }
    };
    auto ff2_epi = [&](int l, float (*hstate)[64],
                       float lgA, float lgB, float lbA, float lbB,
                       float loA, float loB, float lqA, float lqB,
                       bool layer0, int t, const ulonglong2* wp, float (*xbuf)[12]){
        if (!sact) return;
        u64t a0[3], a1[3];
        #pragma unroll
        for (int j=0;j<3;j++){ a0[j] = pk2(sb_b2[l][sm2], 0.f); a1[j] = pk2(sb_b2[l][sm2+1], 0.f); }
        #pragma unroll 8
        for (int p=0;p<64;p++){
            ulonglong2 w = wp[p*32 + scp];
            #pragma unroll
            for (int j=0;j<3;j++){
                u64t z = *(const u64t*)&sh_t1[srw[j]][2*p];
                a0[j] = fma2(z, w.x, a0[j]);
                a1[j] = fma2(z, w.y, a1[j]);
            }
        }
        #pragma unroll
        for (int j=0;j<3;j++){
            float y0 = red2(a0[j]), y1 = red2(a1[j]);
            float sm = y0 + y1, sq = y0*y0 + y1*y1;
            #pragma unroll
            for (int o=16;o;o>>=1){
                sm += __shfl_xor_sync(0xffffffffu, sm, o);
                sq += __shfl_xor_sync(0xffffffffu, sq, o);
            }
            float mean = sm * 0.015625f;
            float rstd = rsqrtf(sq*0.015625f - mean*mean + 1e-5f);
            float2 hv = *(const float2*)&hstate[srw[j]][sm2];
            float z0 = (y0 - mean)*rstd*lgA + lbA + hv.x;
            float z1 = (y1 - mean)*rstd*lgB + lbB + hv.y;
            float sm2_ = z0 + z1, sq2 = z0*z0 + z1*z1;
            #pragma unroll
            for (int o=16;o;o>>=1){
                sm2_ += __shfl_xor_sync(0xffffffffu, sm2_, o);
                sq2  += __shfl_xor_sync(0xffffffffu, sq2,  o);
            }
            float mean2 = sm2_ * 0.015625f;
            float rstd2 = rsqrtf(sq2*0.015625f - mean2*mean2 + 1e-5f);
            float h0 = (z0 - mean2)*rstd2*loA + lqA;
            float h1 = (z1 - mean2)*rstd2*loB + lqB;
            if (svr[j]) *(float2*)&hstate[srw[j]][sm2] = make_float2(h0, h1);
            if (layer0){
                float i0 = h0 + r_rb0a, i1 = h1 + r_rb0b;
                #pragma unroll
                for (int k=0;k<12;k++){
                    float xv = xbuf[srw[j]][k];
                    float2 wv = *(const float2*)&s_rw0[k*64 + sm2];
                    i0 = fmaf(xv, wv.x, i0);
                    i1 = fmaf(xv, wv.y, i1);
                }
                if (svr[j]) *(float2*)&sh_inp[srw[j]][sm2] = make_float2(i0, i1);
            } else {
                u64t oa = pk2(h0 + sb_rb1[sm2],   0.f);
                u64t ob = pk2(h1 + sb_rb1[sm2+1], 0.f);
                #pragma unroll 8
                for (int p=0;p<32;p++){
                    ulonglong2 w = rwu[p*32 + scp];
                    u64t z = *(const u64t*)&sh_inp[srw[j]][2*p];
                    oa = fma2(z, w.x, oa);
                    ob = fma2(z, w.y, ob);
                }
                if (svr[j]) ((float2*)(outbase + ((size_t)srw[j]*512 + t)*64))[scp] = make_float2(red2(oa), red2(ob));
            }
        }
    };

    for (int t=0; t<512; t++){
        float (*xb)[12] = sh_x[t&1];
        float (*xn)[12] = sh_x[(t+1)&1];

        // ---- W1: gates l0 part A (B1: pairs 0..15) ; copy gw0c1->B2, gw0c2->S ----
        cpyp<2048>(B2, gw0g + 2048, tid);
        cpyp<768>(Sp, gw0g + 4096, tid);
        u64t aF[3], aI[3], aG[3], aO[3];
        #pragma unroll
        for (int j=0;j<3;j++){
            aF[j] = pk2(r_gb0f,0.f); aI[j] = pk2(r_gb0i,0.f);
            aG[j] = pk2(r_gb0g,0.f); aO[j] = pk2(r_gb0o,0.f);
        }
        #pragma unroll
        for (int p=0;p<6;p++){                        // k 0..11 from x
            ulonglong2 wfi = B1u[p*128 + gm], wgo = B1u[p*128 + 64 + gm];
            #pragma unroll
            for (int j=0;j<3;j++){
                u64t z = *(const u64t*)&xb[grow[j]][2*p];
                aF[j] = fma2(z, wfi.x, aF[j]); aI[j] = fma2(z, wfi.y, aI[j]);
                aG[j] = fma2(z, wgo.x, aG[j]); aO[j] = fma2(z, wgo.y, aO[j]);
            }
        }
        #pragma unroll 5
        for (int p=6;p<16;p++){                       // k 12..19 from sh_h0
            ulonglong2 wfi = B1u[p*128 + gm], wgo = B1u[p*128 + 64 + gm];
            #pragma unroll
            for (int j=0;j<3;j++){
                u64t z = *(const u64t*)&sh_h0[grow[j]][2*p-12];
                aF[j] = fma2(z, wfi.x, aF[j]); aI[j] = fma2(z, wfi.y, aI[j]);
                aG[j] = fma2(z, wgo.x, aG[j]); aO[j] = fma2(z, wgo.y, aO[j]);
            }
        }
        __syncthreads();                              // S1

        // ---- W2: gates part B (B2: pairs 16..31) + C (S: pairs 32..37) ; copy Wa0->B1 ----
        cpyp<1024>(B1, Wa0_4, tid);
        #pragma unroll 8
        for (int p=16;p<32;p++){
            ulonglong2 wfi = B2u[(p-16)*128 + gm], wgo = B2u[(p-16)*128 + 64 + gm];
            #pragma unroll
            for (int j=0;j<3;j++){
                u64t z = *(const u64t*)&sh_h0[grow[j]][2*p-12];
                aF[j] = fma2(z, wfi.x, aF[j]); aI[j] = fma2(z, wfi.y, aI[j]);
                aG[j] = fma2(z, wgo.x, aG[j]); aO[j] = fma2(z, wgo.y, aO[j]);
            }
        }
        #pragma unroll
        for (int p=32;p<38;p++){
            ulonglong2 wfi = Su[(p-32)*128 + gm], wgo = Su[(p-32)*128 + 64 + gm];
            #pragma unroll
            for (int j=0;j<3;j++){
                u64t z = *(const u64t*)&sh_h0[grow[j]][2*p-12];
                aF[j] = fma2(z, wfi.x, aF[j]); aI[j] = fma2(z, wfi.y, aI[j]);
                aG[j] = fma2(z, wgo.x, aG[j]); aO[j] = fma2(z, wgo.y, aO[j]);
            }
        }
        #pragma unroll
        for (int j=0;j<3;j++){
            float cn = sigmf(red2(aF[j]))*c0s[j] + sigmf(red2(aI[j]))*tanhfast(red2(aG[j]));
            float ht = sigmf(red2(aO[j]))*tanhfast(cn);
            if (gvr[j]){ c0s[j] = cn; sh_hy[grow[j]][gm] = ht; }
        }
        __syncthreads();                              // S2

        // ---- W3: attn0 (B1=Wa0) ; copy w10->B2 ----
        cpyp<2048>(B2, w10_4, tid);
        attn_stage(0, B1u);
        __syncthreads();                              // S3

        // ---- W4: ff1_0 (B2=w10) ; copy w20->B1 ----
        cpyp<2048>(B1, w20_4, tid);
        ff1_stage(0, B2u);
        __syncthreads();                              // S4

        // ---- W5: ff2_epi0 (B1=w20) ; copy gw1 streamed pairs 48..63 -> B2 ----
        cpyp<2048>(B2, gw1g + 6144, tid);
        ff2_epi(0, sh_h0, lg0a, lg0b, lb0a, lb0b, lo0a, lo0b, lq0a, lq0b, true, t, B1u, xb);
        __syncthreads();                              // S5

        // ---- W6: gates l1 (resident pairs 0..47 + B2 pairs 48..63) ; copy Wa1->S ; x(t+1) ----
        cpyp<1024>(Sp, Wa1_4, tid);
        xups(t+1, xn);
        u64t bF[3], bI[3], bG[3], bO[3];
        #pragma unroll
        for (int j=0;j<3;j++){
            bF[j] = pk2(r_gb1f,0.f); bI[j] = pk2(r_gb1i,0.f);
            bG[j] = pk2(r_gb1g,0.f); bO[j] = pk2(r_gb1o,0.f);
        }
        #pragma unroll 8
        for (int p=0;p<32;p++){                       // k 0..63 from sh_inp (resident)
            ulonglong2 wfi = gw1u[p*128 + gm], wgo = gw1u[p*128 + 64 + gm];
            #pragma unroll
            for (int j=0;j<3;j++){
                u64t z = *(const u64t*)&sh_inp[grow[j]][2*p];
                bF[j] = fma2(z, wfi.x, bF[j]); bI[j] = fma2(z, wfi.y, bI[j]);
                bG[j] = fma2(z, wgo.x, bG[j]); bO[j] = fma2(z, wgo.y, bO[j]);
            }
        }
        #pragma unroll 8
        for (int p=32;p<48;p++){                      // k 64..95 from sh_h1 (resident)
            ulonglong2 wfi = gw1u[p*128 + gm], wgo = gw1u[p*128 + 64 + gm];
            #pragma unroll
            for (int j=0;j<3;j++){
                u64t z = *(const u64t*)&sh_h1[grow[j]][2*p-64];
                bF[j] = fma2(z, wfi.x, bF[j]); bI[j] = fma2(z, wfi.y, bI[j]);
                bG[j] = fma2(z, wgo.x, bG[j]); bO[j] = fma2(z, wgo.y, bO[j]);
            }
        }
        #pragma unroll 8
        for (int p=48;p<64;p++){                      // k 96..127 from sh_h1 (streamed B2)
            ulonglong2 wfi = B2u[(p-48)*128 + gm], wgo = B2u[(p-48)*128 + 64 + gm];
            #pragma unroll
            for (int j=0;j<3;j++){
                u64t z = *(const u64t*)&sh_h1[grow[j]][2*p-64];
                bF[j] = fma2(z, wfi.x, bF[j]); bI[j] = fma2(z, wfi.y, bI[j]);
                bG[j] = fma2(z, wgo.x, bG[j]); bO[j] = fma2(z, wgo.y, bO[j]);
            }
        }
        #pragma unroll
        for (int j=0;j<3;j++){
            float cn = sigmf(red2(bF[j]))*c1s[j] + sigmf(red2(bI[j]))*tanhfast(red2(bG[j]));
            float ht = sigmf(red2(bO[j]))*tanhfast(cn);
            if (gvr[j]){ c1s[j] = cn; sh_hy[grow[j]][gm] = ht; }
        }
        __syncthreads();                              // S6

        // ---- W7: attn1 (S=Wa1) ; copy w11->B1 ----
        cpyp<2048>(B1, w11_4, tid);
        attn_stage(1, Su);
        __syncthreads();                              // S7

        // ---- W8: ff1_1 (B1=w11) ; copy w21->B2 ----
        cpyp<2048>(B2, w21_4, tid);
        ff1_stage(1, B1u);
        __syncthreads();                              // S8

        // ---- W9: ff2_epi1+out (B2=w21) ; copy gw0c0->B1 for next step ----
        cpyp<2048>(B1, gw0g, tid);
        ff2_epi(1, sh_h1, lg1a, lg1b, lb1a, lb1b, lo1a, lo1b, lq1a, lq1b, false, t, B2u, xb);
        __syncthreads();                              // S9
    }
}

__global__ void merge_kernel(const float* __restrict__ attn_w, float* __restrict__ out){
    int warp = (blockIdx.x*blockDim.x + threadIdx.x) >> 5;
    int lane = threadIdx.x & 31;
    if (warp >= 512*512) return;
    const size_t SS = 512ull*512*64;
    const float* p = g_outs + (size_t)warp*64;
    float aw0 = attn_w[lane], aw1 = attn_w[lane+32];
    float v0[3], v1[3], sc[3];
    #pragma unroll
    for (int si=0; si<3; si++){
        v0[si] = p[si*SS + lane];
        v1[si] = p[si*SS + lane + 32];
        float d = v0[si]*aw0 + v1[si]*aw1;
        #pragma unroll
        for (int o=16;o;o>>=1) d += __shfl_xor_sync(0xffffffffu, d, o);
        sc[si] = d;
    }
    float mx = fmaxf(sc[0], fmaxf(sc[1], sc[2]));
    float e0 = __expf(sc[0]-mx), e1 = __expf(sc[1]-mx), e2 = __expf(sc[2]-mx);
    float inv = __fdividef(1.0f, e0+e1+e2);
    float wt0 = e0*inv, wt1 = e1*inv, wt2 = e2*inv;
    out[(size_t)warp*64 + lane]      = v0[0]*wt0 + v0[1]*wt1 + v0[2]*wt2;
    out[(size_t)warp*64 + lane + 32] = v1[0]*wt0 + v1[1]*wt1 + v1[2]*wt2;
}

extern "C" void kernel_launch(void* const* d_in, const int* in_sizes, int n_in,
                              void* d_out, int out_size){
    const float* x     = (const float*)d_in[0];
    const float* gw0   = (const float*)d_in[1];
    const float* gb0   = (const float*)d_in[2];
    const float* gw1   = (const float*)d_in[3];
    const float* gb1   = (const float*)d_in[4];
    const float* mi_w  = (const float*)d_in[5];
    const float* mi_b  = (const float*)d_in[6];
    const float* mo_w  = (const float*)d_in[7];
    const float* mo_b  = (const float*)d_in[8];
    const float* w1    = (const float*)d_in[9];
    const float* b1    = (const float*)d_in[10];
    const float* w2    = (const float*)d_in[11];
    const float* b2    = (const float*)d_in[12];
    const float* lag   = (const float*)d_in[13];
    const float* lab   = (const float*)d_in[14];
    const float* logw  = (const float*)d_in[15];
    const float* lob   = (const float*)d_in[16];
    const float* rw0   = (const float*)d_in[17];
    const float* rb0   = (const float*)d_in[18];
    const float* rw1   = (const float*)d_in[19];
    const float* rb1   = (const float*)d_in[20];
    const float* attnw = (const float*)d_in[21];
    float* out = (float*)d_out;

    static int smem_set = 0;
    if (!smem_set){
        cudaFuncSetAttribute(xlstm_kernel, cudaFuncAttributeMaxDynamicSharedMemorySize, DYN_SMEM);
        smem_set = 1;
    }

    pack_gw_kernel<<<(3*128*256 + 255)/256, 256>>>(gw0, gw1);
    pack_t_kernel<<<(6*64*128 + 255)/256, 256>>>(w1, w2, rw1);
    compute_wa_kernel<<<6, 256>>>(mi_w, mi_b, mo_w, mo_b);
    xlstm_kernel<<<NCTA, T, DYN_SMEM>>>(x, gb0, gb1, b1, b2,
                                        lag, lab, logw, lob, rw0, rb0, rb1);
    merge_kernel<<<(512*512*32 + 255)/256, 256>>>(attnw, out);
}

// round 16
// speedup vs baseline: 1.3916x; 1.0698x over previous
#include <cuda_runtime.h>
#include <math.h>

#define NSC   48
#define RMAX  11
#define NCTA  (3*NSC)
#define T     256

#define GW1_RES 6144
#define RW1_OFF 6144
#define B1_OFF  7168
#define B2_OFF  9216
#define S_OFF   11264
#define DYN_SMEM (12288*16)   // 196,608 B

typedef unsigned long long u64t;

__device__ float4 g_gw0p2[3*4864];
__device__ float4 g_gw1p2[3*8192];
__device__ __align__(16) float g_Wa_t[6*4096];
__device__ __align__(16) float g_w1_t[6*8192];
__device__ __align__(16) float g_w2_t[6*8192];
__device__ __align__(16) float g_rw1_t[3*4096];
__device__ float g_ba[6*64];
__device__ float g_outs[3ull*512*512*64];

__device__ __forceinline__ float sigmf(float v){
    return __fdividef(1.0f, 1.0f + __expf(-v));
}
__device__ __forceinline__ float tanhfast(float v){
    return 1.0f - __fdividef(2.0f, __expf(2.0f*v) + 1.0f);
}
__device__ __forceinline__ u64t fma2(u64t a, u64t b, u64t c){
    u64t d;
    asm("fma.rn.f32x2 %0, %1, %2, %3;" : "=l"(d) : "l"(a), "l"(b), "l"(c));
    return d;
}
__device__ __forceinline__ u64t pk2(float lo, float hi){
    u64t r; asm("mov.b64 %0, {%1, %2};" : "=l"(r) : "f"(lo), "f"(hi)); return r;
}
__device__ __forceinline__ float red2(u64t v){
    float lo, hi; asm("mov.b64 {%0, %1}, %2;" : "=f"(lo), "=f"(hi) : "l"(v)); return lo + hi;
}

template<int N>
__device__ __forceinline__ void cpyp(float4* d, const float4* __restrict__ s, int tid){
    #pragma unroll
    for (int i = 0; i < (N + T - 1)/T; i++){
        int j = tid + i*T;
        if (j < N) d[j] = s[j];
    }
}
// copy with 128 threads (warps 4..7), tid2 in 0..127
template<int N>
__device__ __forceinline__ void cpyh(float4* d, const float4* __restrict__ s, int tid2){
    #pragma unroll
    for (int i = 0; i < (N + 127)/128; i++){
        int j = tid2 + i*128;
        if (j < N) d[j] = s[j];
    }
}

__global__ void pack_gw_kernel(const float* __restrict__ gw0, const float* __restrict__ gw1){
    int i = blockIdx.x*blockDim.x + threadIdx.x;
    float* p0 = (float*)g_gw0p2;
    float* p1 = (float*)g_gw1p2;
    if (i < 3*76*256){
        int s = i/(76*256), rem = i%(76*256), k = rem/256, j = rem%256;
        int g = j>>6, m = j&63, p = k>>1, h = k&1;
        int plane = g>>1;
        p0[(s*38 + p)*512 + plane*256 + m*4 + ((g&1)<<1) + h] = gw0[i];
    }
    if (i < 3*128*256){
        int s = i/(128*256), rem = i%(128*256), k = rem/256, j = rem%256;
        int g = j>>6, m = j&63, p = k>>1, h = k&1;
        int plane = g>>1;
        p1[(s*64 + p)*512 + plane*256 + m*4 + ((g&1)<<1) + h] = gw1[i];
    }
}

__global__ void pack_t_kernel(const float* __restrict__ w1, const float* __restrict__ w2,
                              const float* __restrict__ rw1){
    int i = blockIdx.x*blockDim.x + threadIdx.x;
    if (i < 6*64*128){
        int sl = i/(64*128), k = (i/128)%64, n = i%128;
        g_w1_t[((sl*32 + (k>>1))*64 + (n>>1))*4 + ((n&1)<<1) + (k&1)] = w1[i];
    }
    if (i < 6*128*64){
        int sl = i/(128*64), k = (i/64)%128, n = i%64;
        g_w2_t[((sl*64 + (k>>1))*32 + (n>>1))*4 + ((n&1)<<1) + (k&1)] = w2[i];
    }
    if (i < 3*64*64){
        int s = i/(64*64), k = (i/64)%64, n = i%64;
        g_rw1_t[((s*32 + (k>>1))*32 + (n>>1))*4 + ((n&1)<<1) + (k&1)] = rw1[i];
    }
}

__global__ void compute_wa_kernel(const float* __restrict__ mi_w, const float* __restrict__ mi_b,
                                  const float* __restrict__ mo_w, const float* __restrict__ mo_b){
    int sl = blockIdx.x;
    const float* miw = mi_w + (size_t)sl*64*192;
    const float* mow = mo_w + (size_t)sl*64*64;
    for (int idx = threadIdx.x; idx < 64*64; idx += blockDim.x){
        int k = idx>>6, n = idx&63;
        float acc = 0.f;
        #pragma unroll 8
        for (int j=0;j<64;j++) acc += miw[k*192 + 128 + j] * mow[j*64 + n];
        g_Wa_t[((sl*32 + (k>>1))*32 + (n>>1))*4 + ((n&1)<<1) + (k&1)] = acc;
    }
    if (threadIdx.x < 64){
        int n = threadIdx.x;
        float acc = mo_b[sl*64 + n];
        #pragma unroll 8
        for (int j=0;j<64;j++) acc += mi_b[sl*192 + 128 + j] * mow[j*64 + n];
        g_ba[sl*64 + n] = acc;
    }
}

__global__ void __launch_bounds__(T, 1) xlstm_kernel(
    const float* __restrict__ x,
    const float* __restrict__ gb0, const float* __restrict__ gb1,
    const float* __restrict__ b1,  const float* __restrict__ b2,
    const float* __restrict__ lag, const float* __restrict__ lab,
    const float* __restrict__ logw,const float* __restrict__ lob,
    const float* __restrict__ rw0, const float* __restrict__ rb0,
    const float* __restrict__ rb1)
{
    const int cta = blockIdx.x;
    const int s   = cta / NSC;
    const int ci  = cta % NSC;
    const int base  = (ci < 32) ? ci*11 : 352 + (ci-32)*10;
    const int nrows = (ci < 32) ? 11 : 10;
    const int tid  = threadIdx.x;
    const int lane = tid & 31;
    const int wrp  = tid >> 5;          // 0..7
    const int tid2 = tid - 128;         // copy-warp index (warps 4..7)
    const bool cw  = (wrp >= 4);        // copy warps

    // gates/ff1: 4 warps (0..3) = 2 col-halves x 2 row-groups, 6 rows/thread
    const bool gact = (wrp < 4);
    const int colh = wrp & 1;
    const int g2   = (wrp >> 1) & 1;
    const int gm   = colh*32 + lane;    // gate col / ff1 colpair
    const int fn2  = gm*2;
    int grow[6]; bool gvr[6];
    #pragma unroll
    for (int j=0;j<6;j++){ int r = g2 + 2*j; gvr[j] = (r < nrows); grow[j] = gvr[j] ? r : 0; }

    // attn / ff2+epilogue / out: 4 warps x 3 rows, lane = colpair
    const bool sact = (wrp < 4);
    const int scp   = lane;
    const int sm2   = lane*2;
    int srw[3]; bool svr[3];
    #pragma unroll
    for (int j=0;j<3;j++){ int r = wrp + 4*j; svr[j] = sact && (r < nrows); srw[j] = (r < nrows) ? r : 0; }

    extern __shared__ float4 dynsm[];
    float4* B1 = dynsm + B1_OFF;
    float4* B2 = dynsm + B2_OFF;
    float4* Sp = dynsm + S_OFF;
    const ulonglong2* gw1u = (const ulonglong2*)dynsm;
    const ulonglong2* rwu  = (const ulonglong2*)(dynsm + RW1_OFF);
    const ulonglong2* B1u  = (const ulonglong2*)B1;
    const ulonglong2* B2u  = (const ulonglong2*)B2;
    const ulonglong2* Su   = (const ulonglong2*)Sp;

    __shared__ __align__(16) float sh_h0[RMAX][64], sh_h1[RMAX][64];
    __shared__ __align__(16) float sh_x[2][RMAX][12];
    __shared__ __align__(16) float sh_hy[RMAX][64];
    __shared__ __align__(16) float sh_a[RMAX][64];
    __shared__ __align__(16) float sh_t1[RMAX][128];
    __shared__ __align__(16) float sh_inp[RMAX][64];
    __shared__ __align__(16) float sb_ba[2][64];
    __shared__ __align__(16) float sb_b1[2][128];
    __shared__ __align__(16) float sb_b2[2][64];
    __shared__ __align__(16) float sb_rb1[64];
    __shared__ __align__(16) float s_rw0[12*64];

    const float4* gw0g = g_gw0p2 + (size_t)s*4864;
    const float4* gw1g = g_gw1p2 + (size_t)s*8192;
    const float4* Wa0_4 = (const float4*)g_Wa_t + (size_t)(s*2+0)*1024;
    const float4* Wa1_4 = (const float4*)g_Wa_t + (size_t)(s*2+1)*1024;
    const float4* w10_4 = (const float4*)g_w1_t + (size_t)(s*2+0)*2048;
    const float4* w11_4 = (const float4*)g_w1_t + (size_t)(s*2+1)*2048;
    const float4* w20_4 = (const float4*)g_w2_t + (size_t)(s*2+0)*2048;
    const float4* w21_4 = (const float4*)g_w2_t + (size_t)(s*2+1)*2048;

    const int Li  = (s==0) ? 170 : (s==1 ? 512 : 256);
    const int st0 = (s==0) ? 342 : (s==1 ? 0   : 256);
    const float scf = (float)Li / 512.0f;

    // x upsample executed by copy warps (128 threads)
    auto xups_h = [&](int tt, float (*xbuf)[12]){
        float srcf = fmaxf((tt + 0.5f) * scf - 0.5f, 0.0f);
        int i0 = (int)srcf;
        if (i0 > Li-1) i0 = Li-1;
        int i1 = min(i0+1, Li-1);
        float wu = srcf - (float)i0;
        for (int i = tid2; i < nrows*12; i += 128){
            int r = i/12, k = i%12;
            const float* xb = x + ((size_t)(base+r)*512 + st0)*12;
            float va = xb[i0*12 + k], vb = xb[i1*12 + k];
            xbuf[r][k] = va*(1.0f - wu) + vb*wu;
        }
    };

    // ---- prologue (all threads) ----
    {
        for (int i=tid;i<GW1_RES;i+=T) dynsm[i] = gw1g[i];
        const float4* rw1s = (const float4*)g_rw1_t + (size_t)s*1024;
        for (int i=tid;i<1024;i+=T) dynsm[RW1_OFF + i] = rw1s[i];
        const float* rw0s = rw0 + (size_t)s*768;
        for (int i=tid;i<768;i+=T) s_rw0[i] = rw0s[i];
        for (int i = tid; i < RMAX*64; i += T){ ((float*)sh_h0)[i] = 0.f; ((float*)sh_h1)[i] = 0.f; }
        if (tid < 128){
            sb_b1[0][tid] = b1[(s*2+0)*128 + tid];
            sb_b1[1][tid] = b1[(s*2+1)*128 + tid];
        }
        if (tid < 64){
            sb_ba[0][tid] = g_ba[(s*2+0)*64 + tid];
            sb_ba[1][tid] = g_ba[(s*2+1)*64 + tid];
            sb_b2[0][tid] = b2[(s*2+0)*64 + tid];
            sb_b2[1][tid] = b2[(s*2+1)*64 + tid];
            sb_rb1[tid]   = rb1[s*64 + tid];
        }
        cpyp<2048>(B1, gw0g, tid);      // gw0 pairs 0..15
        {   // x(t=0), all threads
            float srcf = fmaxf(0.5f * scf - 0.5f, 0.0f);
            int i0 = (int)srcf;
            if (i0 > Li-1) i0 = Li-1;
            int i1 = min(i0+1, Li-1);
            float wu = srcf - (float)i0;
            if (tid < nrows*12){
                int r = tid/12, k = tid%12;
                const float* xb = x + ((size_t)(base+r)*512 + st0)*12;
                float va = xb[i0*12 + k], vb = xb[i1*12 + k];
                sh_x[0][r][k] = va*(1.0f - wu) + vb*wu;
            }
        }
    }
    const float r_gb0f = gb0[s*256 + gm],     r_gb0i = gb0[s*256 + 64 + gm];
    const float r_gb0g = gb0[s*256 + 128+gm], r_gb0o = gb0[s*256 + 192 + gm];
    const float r_gb1f = gb1[s*256 + gm],     r_gb1i = gb1[s*256 + 64 + gm];
    const float r_gb1g = gb1[s*256 + 128+gm], r_gb1o = gb1[s*256 + 192 + gm];
    const float lg0a = lag[(s*2+0)*64+sm2], lg0b = lag[(s*2+0)*64+sm2+1];
    const float lb0a = lab[(s*2+0)*64+sm2], lb0b = lab[(s*2+0)*64+sm2+1];
    const float lo0a = logw[(s*2+0)*64+sm2],lo0b = logw[(s*2+0)*64+sm2+1];
    const float lq0a = lob[(s*2+0)*64+sm2], lq0b = lob[(s*2+0)*64+sm2+1];
    const float lg1a = lag[(s*2+1)*64+sm2], lg1b = lag[(s*2+1)*64+sm2+1];
    const float lb1a = lab[(s*2+1)*64+sm2], lb1b = lab[(s*2+1)*64+sm2+1];
    const float lo1a = logw[(s*2+1)*64+sm2],lo1b = logw[(s*2+1)*64+sm2+1];
    const float lq1a = lob[(s*2+1)*64+sm2], lq1b = lob[(s*2+1)*64+sm2+1];
    const float r_rb0a = rb0[s*64+sm2], r_rb0b = rb0[s*64+sm2+1];
    __syncthreads();

    float c0s[6] = {0,0,0,0,0,0}, c1s[6] = {0,0,0,0,0,0};
    float* outbase = g_outs + ((size_t)s*512 + base)*512*64;

    auto attn_stage = [&](int l, const ulonglong2* wp){
        u64t a0[3], a1[3];
        #pragma unroll
        for (int j=0;j<3;j++){ a0[j] = pk2(sb_ba[l][sm2], 0.f); a1[j] = pk2(sb_ba[l][sm2+1], 0.f); }
        #pragma unroll 8
        for (int p=0;p<32;p++){
            ulonglong2 w = wp[p*32 + scp];
            #pragma unroll
            for (int j=0;j<3;j++){
                u64t z = *(const u64t*)&sh_hy[srw[j]][2*p];
                a0[j] = fma2(z, w.x, a0[j]);
                a1[j] = fma2(z, w.y, a1[j]);
            }
        }
        #pragma unroll
        for (int j=0;j<3;j++)
            if (svr[j]) *(float2*)&sh_a[srw[j]][sm2] = make_float2(red2(a0[j]), red2(a1[j]));
    };
    // ff1: 4 warps x 6 rows
    auto ff1_stage = [&](int l, const ulonglong2* wp){
        u64t t0[6], t1[6];
        #pragma unroll
        for (int j=0;j<6;j++){ t0[j] = pk2(sb_b1[l][fn2], 0.f); t1[j] = pk2(sb_b1[l][fn2+1], 0.f); }
        #pragma unroll 8
        for (int p=0;p<32;p++){
            ulonglong2 w = wp[p*64 + gm];
            #pragma unroll
            for (int j=0;j<6;j++){
                u64t z = *(const u64t*)&sh_a[grow[j]][2*p];
                t0[j] = fma2(z, w.x, t0[j]);
                t1[j] = fma2(z, w.y, t1[j]);
            }
        }
        const float c = 0.7071067811865475f;
        #pragma unroll
        for (int j=0;j<6;j++){
            float v0 = red2(t0[j]), v1 = red2(t1[j]);
            float g0 = 0.5f*v0*(1.0f + erff(v0*c));
            float g1 = 0.5f*v1*(1.0f + erff(v1*c));
            if (gvr[j]) *(float2*)&sh_t1[grow[j]][fn2] = make_float2(g0, g1);
        }
    };
    auto ff2_epi = [&](int l, float (*hstate)[64],
                       float lgA, float lgB, float lbA, float lbB,
                       float loA, float loB, float lqA, float lqB,
                       bool layer0, int t, const ulonglong2* wp, float (*xbuf)[12]){
        u64t a0[3], a1[3];
        #pragma unroll
        for (int j=0;j<3;j++){ a0[j] = pk2(sb_b2[l][sm2], 0.f); a1[j] = pk2(sb_b2[l][sm2+1], 0.f); }
        #pragma unroll 8
        for (int p=0;p<64;p++){
            ulonglong2 w = wp[p*32 + scp];
            #pragma unroll
            for (int j=0;j<3;j++){
                u64t z = *(const u64t*)&sh_t1[srw[j]][2*p];
                a0[j] = fma2(z, w.x, a0[j]);
                a1[j] = fma2(z, w.y, a1[j]);
            }
        }
        #pragma unroll
        for (int j=0;j<3;j++){
            float y0 = red2(a0[j]), y1 = red2(a1[j]);
            float sm = y0 + y1, sq = y0*y0 + y1*y1;
            #pragma unroll
            for (int o=16;o;o>>=1){
                sm += __shfl_xor_sync(0xffffffffu, sm, o);
                sq += __shfl_xor_sync(0xffffffffu, sq, o);
            }
            float mean = sm * 0.015625f;
            float rstd = rsqrtf(sq*0.015625f - mean*mean + 1e-5f);
            float2 hv = *(const float2*)&hstate[srw[j]][sm2];
            float z0 = (y0 - mean)*rstd*lgA + lbA + hv.x;
            float z1 = (y1 - mean)*rstd*lgB + lbB + hv.y;
            float sm2_ = z0 + z1, sq2 = z0*z0 + z1*z1;
            #pragma unroll
            for (int o=16;o;o>>=1){
                sm2_ += __shfl_xor_sync(0xffffffffu, sm2_, o);
                sq2  += __shfl_xor_sync(0xffffffffu, sq2,  o);
            }
            float mean2 = sm2_ * 0.015625f;
            float rstd2 = rsqrtf(sq2*0.015625f - mean2*mean2 + 1e-5f);
            float h0 = (z0 - mean2)*rstd2*loA + lqA;
            float h1 = (z1 - mean2)*rstd2*loB + lqB;
            if (svr[j]) *(float2*)&hstate[srw[j]][sm2] = make_float2(h0, h1);
            if (layer0){
                float i0 = h0 + r_rb0a, i1 = h1 + r_rb0b;
                #pragma unroll
                for (int k=0;k<12;k++){
                    float xv = xbuf[srw[j]][k];
                    float2 wv = *(const float2*)&s_rw0[k*64 + sm2];
                    i0 = fmaf(xv, wv.x, i0);
                    i1 = fmaf(xv, wv.y, i1);
                }
                if (svr[j]) *(float2*)&sh_inp[srw[j]][sm2] = make_float2(i0, i1);
            } else {
                u64t oa = pk2(h0 + sb_rb1[sm2],   0.f);
                u64t ob = pk2(h1 + sb_rb1[sm2+1], 0.f);
                #pragma unroll 8
                for (int p=0;p<32;p++){
                    ulonglong2 w = rwu[p*32 + scp];
                    u64t z = *(const u64t*)&sh_inp[srw[j]][2*p];
                    oa = fma2(z, w.x, oa);
                    ob = fma2(z, w.y, ob);
                }
                if (svr[j]) ((float2*)(outbase + ((size_t)srw[j]*512 + t)*64))[scp] = make_float2(red2(oa), red2(ob));
            }
        }
    };

    for (int t=0; t<512; t++){
        float (*xb)[12] = sh_x[t&1];
        float (*xn)[12] = sh_x[(t+1)&1];

        u64t aF[6], aI[6], aG[6], aO[6];
        // ---- W1: gates l0 part A (B1 pairs 0..15) | copies gw0c1->B2, gw0c2->S ----
        if (gact){
            #pragma unroll
            for (int j=0;j<6;j++){
                aF[j] = pk2(r_gb0f,0.f); aI[j] = pk2(r_gb0i,0.f);
                aG[j] = pk2(r_gb0g,0.f); aO[j] = pk2(r_gb0o,0.f);
            }
            #pragma unroll
            for (int p=0;p<6;p++){
                ulonglong2 wfi = B1u[p*128 + gm], wgo = B1u[p*128 + 64 + gm];
                #pragma unroll
                for (int j=0;j<6;j++){
                    u64t z = *(const u64t*)&xb[grow[j]][2*p];
                    aF[j] = fma2(z, wfi.x, aF[j]); aI[j] = fma2(z, wfi.y, aI[j]);
                    aG[j] = fma2(z, wgo.x, aG[j]); aO[j] = fma2(z, wgo.y, aO[j]);
                }
            }
            #pragma unroll 5
            for (int p=6;p<16;p++){
                ulonglong2 wfi = B1u[p*128 + gm], wgo = B1u[p*128 + 64 + gm];
                #pragma unroll
                for (int j=0;j<6;j++){
                    u64t z = *(const u64t*)&sh_h0[grow[j]][2*p-12];
                    aF[j] = fma2(z, wfi.x, aF[j]); aI[j] = fma2(z, wfi.y, aI[j]);
                    aG[j] = fma2(z, wgo.x, aG[j]); aO[j] = fma2(z, wgo.y, aO[j]);
                }
            }
        } else {
            cpyh<2048>(B2, gw0g + 2048, tid2);
            cpyh<768>(Sp, gw0g + 4096, tid2);
        }
        __syncthreads();                              // S1

        // ---- W2: gates part B (B2 16..31) + C (S 32..37) | copy Wa0->B1 ----
        if (gact){
            #pragma unroll 8
            for (int p=16;p<32;p++){
                ulonglong2 wfi = B2u[(p-16)*128 + gm], wgo = B2u[(p-16)*128 + 64 + gm];
                #pragma unroll
                for (int j=0;j<6;j++){
                    u64t z = *(const u64t*)&sh_h0[grow[j]][2*p-12];
                    aF[j] = fma2(z, wfi.x, aF[j]); aI[j] = fma2(z, wfi.y, aI[j]);
                    aG[j] = fma2(z, wgo.x, aG[j]); aO[j] = fma2(z, wgo.y, aO[j]);
                }
            }
            #pragma unroll
            for (int p=32;p<38;p++){
                ulonglong2 wfi = Su[(p-32)*128 + gm], wgo = Su[(p-32)*128 + 64 + gm];
                #pragma unroll
                for (int j=0;j<6;j++){
                    u64t z = *(const u64t*)&sh_h0[grow[j]][2*p-12];
                    aF[j] = fma2(z, wfi.x, aF[j]); aI[j] = fma2(z, wfi.y, aI[j]);
                    aG[j] = fma2(z, wgo.x, aG[j]); aO[j] = fma2(z, wgo.y, aO[j]);
                }
            }
            #pragma unroll
            for (int j=0;j<6;j++){
                float cn = sigmf(red2(aF[j]))*c0s[j] + sigmf(red2(aI[j]))*tanhfast(red2(aG[j]));
                float ht = sigmf(red2(aO[j]))*tanhfast(cn);
                if (gvr[j]){ c0s[j] = cn; sh_hy[grow[j]][gm] = ht; }
            }
        } else {
            cpyh<1024>(B1, Wa0_4, tid2);
        }
        __syncthreads();                              // S2

        // ---- W3: attn0 (B1=Wa0) | copy w10->B2 ----
        if (sact) attn_stage(0, B1u);
        else      cpyh<2048>(B2, w10_4, tid2);
        __syncthreads();                              // S3

        // ---- W4: ff1_0 (B2=w10) | copy w20->B1 ----
        if (gact) ff1_stage(0, B2u);
        else      cpyh<2048>(B1, w20_4, tid2);
        __syncthreads();                              // S4

        // ---- W5: ff2_epi0 (B1=w20) | copy gw1 pairs 48..63 -> B2 ----
        if (sact) ff2_epi(0, sh_h0, lg0a, lg0b, lb0a, lb0b, lo0a, lo0b, lq0a, lq0b, true, t, B1u, xb);
        else      cpyh<2048>(B2, gw1g + 6144, tid2);
        __syncthreads();                              // S5

        // ---- W6: gates l1 (resident 0..47 + B2 48..63) | copy Wa1->S, x(t+1) ----
        if (gact){
            #pragma unroll
            for (int j=0;j<6;j++){
                aF[j] = pk2(r_gb1f,0.f); aI[j] = pk2(r_gb1i,0.f);
                aG[j] = pk2(r_gb1g,0.f); aO[j] = pk2(r_gb1o,0.f);
            }
            #pragma unroll 8
            for (int p=0;p<32;p++){
                ulonglong2 wfi = gw1u[p*128 + gm], wgo = gw1u[p*128 + 64 + gm];
                #pragma unroll
                for (int j=0;j<6;j++){
                    u64t z = *(const u64t*)&sh_inp[grow[j]][2*p];
                    aF[j] = fma2(z, wfi.x, aF[j]); aI[j] = fma2(z, wfi.y, aI[j]);
                    aG[j] = fma2(z, wgo.x, aG[j]); aO[j] = fma2(z, wgo.y, aO[j]);
                }
            }
            #pragma unroll 8
            for (int p=32;p<48;p++){
                ulonglong2 wfi = gw1u[p*128 + gm], wgo = gw1u[p*128 + 64 + gm];
                #pragma unroll
                for (int j=0;j<6;j++){
                    u64t z = *(const u64t*)&sh_h1[grow[j]][2*p-64];
                    aF[j] = fma2(z, wfi.x, aF[j]); aI[j] = fma2(z, wfi.y, aI[j]);
                    aG[j] = fma2(z, wgo.x, aG[j]); aO[j] = fma2(z, wgo.y, aO[j]);
                }
            }
            #pragma unroll 8
            for (int p=48;p<64;p++){
                ulonglong2 wfi = B2u[(p-48)*128 + gm], wgo = B2u[(p-48)*128 + 64 + gm];
                #pragma unroll
                for (int j=0;j<6;j++){
                    u64t z = *(const u64t*)&sh_h1[grow[j]][2*p-64];
                    aF[j] = fma2(z, wfi.x, aF[j]); aI[j] = fma2(z, wfi.y, aI[j]);
                    aG[j] = fma2(z, wgo.x, aG[j]); aO[j] = fma2(z, wgo.y, aO[j]);
                }
            }
            #pragma unroll
            for (int j=0;j<6;j++){
                float cn = sigmf(red2(aF[j]))*c1s[j] + sigmf(red2(aI[j]))*tanhfast(red2(aG[j]));
                float ht = sigmf(red2(aO[j]))*tanhfast(cn);
                if (gvr[j]){ c1s[j] = cn; sh_hy[grow[j]][gm] = ht; }
            }
        } else {
            cpyh<1024>(Sp, Wa1_4, tid2);
            xups_h(t+1, xn);
        }
        __syncthreads();                              // S6

        // ---- W7: attn1 (S=Wa1) | copy w11->B1 ----
        if (sact) attn_stage(1, Su);
        else      cpyh<2048>(B1, w11_4, tid2);
        __syncthreads();                              // S7

        // ---- W8: ff1_1 (B1=w11) | copy w21->B2 ----
        if (gact) ff1_stage(1, B1u);
        else      cpyh<2048>(B2, w21_4, tid2);
        __syncthreads();                              // S8

        // ---- W9: ff2_epi1+out (B2=w21) | copy gw0c0->B1 ----
        if (sact) ff2_epi(1, sh_h1, lg1a, lg1b, lb1a, lb1b, lo1a, lo1b, lq1a, lq1b, false, t, B2u, xb);
        else      cpyh<2048>(B1, gw0g, tid2);
        __syncthreads();                              // S9
    }
}

__global__ void merge_kernel(const float* __restrict__ attn_w, float* __restrict__ out){
    int warp = (blockIdx.x*blockDim.x + threadIdx.x) >> 5;
    int lane = threadIdx.x & 31;
    if (warp >= 512*512) return;
    const size_t SS = 512ull*512*64;
    const float* p = g_outs + (size_t)warp*64;
    float aw0 = attn_w[lane], aw1 = attn_w[lane+32];
    float v0[3], v1[3], sc[3];
    #pragma unroll
    for (int si=0; si<3; si++){
        v0[si] = p[si*SS + lane];
        v1[si] = p[si*SS + lane + 32];
        float d = v0[si]*aw0 + v1[si]*aw1;
        #pragma unroll
        for (int o=16;o;o>>=1) d += __shfl_xor_sync(0xffffffffu, d, o);
        sc[si] = d;
    }
    float mx = fmaxf(sc[0], fmaxf(sc[1], sc[2]));
    float e0 = __expf(sc[0]-mx), e1 = __expf(sc[1]-mx), e2 = __expf(sc[2]-mx);
    float inv = __fdividef(1.0f, e0+e1+e2);
    float wt0 = e0*inv, wt1 = e1*inv, wt2 = e2*inv;
    out[(size_t)warp*64 + lane]      = v0[0]*wt0 + v0[1]*wt1 + v0[2]*wt2;
    out[(size_t)warp*64 + lane + 32] = v1[0]*wt0 + v1[1]*wt1 + v1[2]*wt2;
}

extern "C" void kernel_launch(void* const* d_in, const int* in_sizes, int n_in,
                              void* d_out, int out_size){
    const float* x     = (const float*)d_in[0];
    const float* gw0   = (const float*)d_in[1];
    const float* gb0   = (const float*)d_in[2];
    const float* gw1   = (const float*)d_in[3];
    const float* gb1   = (const float*)d_in[4];
    const float* mi_w  = (const float*)d_in[5];
    const float* mi_b  = (const float*)d_in[6];
    const float* mo_w  = (const float*)d_in[7];
    const float* mo_b  = (const float*)d_in[8];
    const float* w1    = (const float*)d_in[9];
    const float* b1    = (const float*)d_in[10];
    const float* w2    = (const float*)d_in[11];
    const float* b2    = (const float*)d_in[12];
    const float* lag   = (const float*)d_in[13];
    const float* lab   = (const float*)d_in[14];
    const float* logw  = (const float*)d_in[15];
    const float* lob   = (const float*)d_in[16];
    const float* rw0   = (const float*)d_in[17];
    const float* rb0   = (const float*)d_in[18];
    const float* rw1   = (const float*)d_in[19];
    const float* rb1   = (const float*)d_in[20];
    const float* attnw = (const float*)d_in[21];
    float* out = (float*)d_out;

    static int smem_set = 0;
    if (!smem_set){
        cudaFuncSetAttribute(xlstm_kernel, cudaFuncAttributeMaxDynamicSharedMemorySize, DYN_SMEM);
        smem_set = 1;
    }

    pack_gw_kernel<<<(3*128*256 + 255)/256, 256>>>(gw0, gw1);
    pack_t_kernel<<<(6*64*128 + 255)/256, 256>>>(w1, w2, rw1);
    compute_wa_kernel<<<6, 256>>>(mi_w, mi_b, mo_w, mo_b);
    xlstm_kernel<<<NCTA, T, DYN_SMEM>>>(x, gb0, gb1, b1, b2,
                                        lag, lab, logw, lob, rw0, rb0, rb1);
    merge_kernel<<<(512*512*32 + 255)/256, 256>>>(attnw, out);
}